// round 10
// baseline (speedup 1.0000x reference)
#include <cuda_runtime.h>
#include <cuda_fp16.h>
#include <cstdint>
#include <cstddef>

#define S_LEN 2048
#define B_DIM 8
#define E_DIM 1024
#define M_TOT (S_LEN*B_DIM)      // 16384
#define CH    (B_DIM*E_DIM)      // 8192
#define NCHUNK 64
#define CLEN  (S_LEN/NCHUNK)     // 32
#define CH4   (CH/4)             // 2048

// ---------------- scratch (device globals; no allocation allowed) ------------
__device__ __half g_xk[(size_t)M_TOT*E_DIM];
__device__ __half g_xv[(size_t)M_TOT*E_DIM];
__device__ __half g_r [(size_t)M_TOT*E_DIM];
__device__ float g_k [(size_t)M_TOT*E_DIM];
__device__ float g_v [(size_t)M_TOT*E_DIM];
__device__ __half g_wkt[(size_t)E_DIM*E_DIM];
__device__ __half g_wvt[(size_t)E_DIM*E_DIM];
__device__ __half g_wot[(size_t)E_DIM*E_DIM];
__device__ float g_agg[3*NCHUNK*CH];
__device__ float g_pre[3*NCHUNK*CH];

// ---------------- helpers ----------------------------------------------------
__device__ __forceinline__ uint32_t smem_addr(const void* p) {
    uint32_t a;
    asm("{ .reg .u64 t; cvta.to.shared.u64 t, %1; cvt.u32.u64 %0, t; }" : "=r"(a) : "l"(p));
    return a;
}
#define CP_ASYNC16(dst, src) \
    asm volatile("cp.async.cg.shared.global [%0], [%1], 16;" :: "r"(dst), "l"(src) : "memory")
#define CP_COMMIT() asm volatile("cp.async.commit_group;" ::: "memory")
#define CP_WAIT(n)  asm volatile("cp.async.wait_group %0;" :: "n"(n) : "memory")

#define LDSM4(r, addr) \
    asm volatile("ldmatrix.sync.aligned.m8n8.x4.shared.b16 {%0,%1,%2,%3}, [%4];" \
        : "=r"((r)[0]), "=r"((r)[1]), "=r"((r)[2]), "=r"((r)[3]) : "r"(addr))

__device__ __forceinline__ void mma_f16(float c[4], const uint32_t a[4], const uint32_t b[2]) {
    asm volatile(
        "mma.sync.aligned.m16n8k16.row.col.f32.f16.f16.f32 "
        "{%0,%1,%2,%3}, {%4,%5,%6,%7}, {%8,%9}, {%0,%1,%2,%3};\n"
        : "+f"(c[0]), "+f"(c[1]), "+f"(c[2]), "+f"(c[3])
        : "r"(a[0]), "r"(a[1]), "r"(a[2]), "r"(a[3]), "r"(b[0]), "r"(b[1]));
}

// ============================================================
// 1) fused prep: token mix + fp16 quantize  AND  3x weight transpose
// ============================================================
#define MIXB (M_TOT*E_DIM/4/256)   // 16384

__global__ void prep_kernel(const float* __restrict__ x,
                            const float* __restrict__ tmrkv,
                            const float* __restrict__ Wk,
                            const float* __restrict__ Wv,
                            const float* __restrict__ Wout) {
    __shared__ float t[32][33];
    int blk = blockIdx.x;
    int tid = threadIdx.x;

    if (blk < MIXB) {
        int i4  = blk * 256 + tid;
        int idx = i4 * 4;
        int e   = idx & (E_DIM - 1);
        float4 xc = *(const float4*)(x + idx);
        float4 xp = make_float4(0.f, 0.f, 0.f, 0.f);
        if (idx >= CH) xp = *(const float4*)(x + idx - CH);
        float4 mk = *(const float4*)(tmrkv + E_DIM   + e);
        float4 mv = *(const float4*)(tmrkv + 2*E_DIM + e);
        float ok[4], ov[4];
        ok[0] = mk.x*xc.x + (1.f-mk.x)*xp.x;  ov[0] = mv.x*xc.x + (1.f-mv.x)*xp.x;
        ok[1] = mk.y*xc.y + (1.f-mk.y)*xp.y;  ov[1] = mv.y*xc.y + (1.f-mv.y)*xp.y;
        ok[2] = mk.z*xc.z + (1.f-mk.z)*xp.z;  ov[2] = mv.z*xc.z + (1.f-mv.z)*xp.z;
        ok[3] = mk.w*xc.w + (1.f-mk.w)*xp.w;  ov[3] = mv.w*xc.w + (1.f-mv.w)*xp.w;
        ushort4 kq, vq;
        kq.x = __half_as_ushort(__float2half_rn(ok[0]));
        kq.y = __half_as_ushort(__float2half_rn(ok[1]));
        kq.z = __half_as_ushort(__float2half_rn(ok[2]));
        kq.w = __half_as_ushort(__float2half_rn(ok[3]));
        vq.x = __half_as_ushort(__float2half_rn(ov[0]));
        vq.y = __half_as_ushort(__float2half_rn(ov[1]));
        vq.z = __half_as_ushort(__float2half_rn(ov[2]));
        vq.w = __half_as_ushort(__float2half_rn(ov[3]));
        *(ushort4*)((unsigned short*)g_xk + idx) = kq;
        *(ushort4*)((unsigned short*)g_xv + idx) = vq;
    } else {
        int wb   = blk - MIXB;
        int widx = wb >> 10;          // 0,1,2
        int tb   = wb & 1023;
        const float* W = (widx == 0) ? Wk : (widx == 1) ? Wv : Wout;
        __half* T = (widx == 0) ? g_wkt : (widx == 1) ? g_wvt : g_wot;
        int bx = (tb & 31) * 32;      // n block
        int by = (tb >> 5) * 32;      // k block
        int tx = tid & 31, ty = tid >> 5;   // 32 x 8
        for (int j = ty; j < 32; j += 8)
            t[j][tx] = W[(size_t)(by + j) * E_DIM + bx + tx];
        __syncthreads();
        for (int j = ty; j < 32; j += 8) {
            float v = t[tx][j];
            T[(size_t)(bx + j) * E_DIM + by + tx] = __float2half_rn(v);
        }
    }
}

// ============================================================
// 2) 1-product fp16 GEMM, 256x128 tile, 512 threads (16 warps, 4x4)
//    m16n8k16 + ldmatrix + XOR swizzle + 4-stage cp.async, 1 sync/iter
// ============================================================
#define BM 256
#define BN 128
#define BK 32
#define A_TILE_B 16384             // 256 rows * 64 bytes
#define B_TILE_B 8192              // 128 rows * 64 bytes
#define STAGE_B (A_TILE_B + B_TILE_B)   // 24576
#define NSTG 4
#define GEMM_SMEM (NSTG*STAGE_B)   // 98304

__global__ void __launch_bounds__(512, 1)
gemm_f16_1p(const __half* __restrict__ Aq, const __half* __restrict__ Bq,
            float* __restrict__ C) {
    extern __shared__ uint32_t smem[];

    int tid  = threadIdx.x;
    int warp = tid >> 5, lane = tid & 31;
    int wm = warp & 3, wn = warp >> 2;             // 4 x 4 warps
    int bm = blockIdx.y * BM, bn = blockIdx.x * BN;

    const char* Asrc = (const char*)(Aq + (size_t)bm * E_DIM);
    const char* Bsrc = (const char*)(Bq + (size_t)bn * E_DIM);
    uint32_t sbase = smem_addr(smem);

    auto load_tile = [&](int kt, int stg) {
        uint32_t dst0 = sbase + (uint32_t)stg * STAGE_B;
        int koff = kt * (BK*2);    // byte offset along K
        // A: 256 rows x 4 chunks = 1024 chunk-loads over 512 threads
        #pragma unroll
        for (int i = 0; i < 2; i++) {
            int f = tid + i*512;
            int row = f >> 2, ch = f & 3;
            int sw = ch ^ ((row >> 1) & 3);
            CP_ASYNC16(dst0 + row*64 + sw*16,
                       Asrc + (size_t)row * (E_DIM*2) + koff + ch*16);
        }
        // B: 128 rows x 4 chunks = 512 chunk-loads
        {
            int row = tid >> 2, ch = tid & 3;
            int sw = ch ^ ((row >> 1) & 3);
            CP_ASYNC16(dst0 + A_TILE_B + row*64 + sw*16,
                       Bsrc + (size_t)row * (E_DIM*2) + koff + ch*16);
        }
    };

    // ---- ldmatrix lane addresses (ks=0; ks=1 is XOR 32) ----
    int lm = lane & 7, lg = lane >> 3;   // lg = matrix index 0..3
    uint32_t aoff[4];
    #pragma unroll
    for (int mt = 0; mt < 4; mt++) {
        int row = wm*64 + mt*16 + (lg & 1)*8 + lm;
        int swc = (lg >> 1) ^ ((row >> 1) & 3);
        aoff[mt] = (uint32_t)(row*64 + swc*16);
    }
    uint32_t boff[2];
    #pragma unroll
    for (int j = 0; j < 2; j++) {
        int row = wn*32 + j*16 + (lg >> 1)*8 + lm;
        int swc = (lg & 1) ^ ((row >> 1) & 3);
        boff[j] = (uint32_t)(row*64 + swc*16);
    }

    float acc[4][4][4];
    #pragma unroll
    for (int mt = 0; mt < 4; mt++)
        #pragma unroll
        for (int nt = 0; nt < 4; nt++)
            #pragma unroll
            for (int q = 0; q < 4; q++) acc[mt][nt][q] = 0.f;

    const int NK = E_DIM / BK;   // 32
    load_tile(0, 0); CP_COMMIT();
    load_tile(1, 1); CP_COMMIT();
    load_tile(2, 2); CP_COMMIT();

    for (int kt = 0; kt < NK; kt++) {
        int stg = kt % NSTG;
        if (kt == NK - 1) { CP_WAIT(0); } else { CP_WAIT(2); }
        __syncthreads();
        if (kt + 3 < NK) { load_tile(kt + 3, (kt + 3) % NSTG); CP_COMMIT(); }

        uint32_t tA = sbase + (uint32_t)stg * STAGE_B;
        uint32_t tB = tA + A_TILE_B;

        #pragma unroll
        for (int ks = 0; ks < 2; ks++) {
            uint32_t ksx = (uint32_t)(ks * 32);
            uint32_t aq[4][4], bq[4][2];
            #pragma unroll
            for (int mt = 0; mt < 4; mt++)
                LDSM4(aq[mt], tA + (aoff[mt] ^ ksx));
            #pragma unroll
            for (int j = 0; j < 2; j++) {
                uint32_t rb[4];
                LDSM4(rb, tB + (boff[j] ^ ksx));
                bq[2*j][0] = rb[0]; bq[2*j][1] = rb[1];
                bq[2*j+1][0] = rb[2]; bq[2*j+1][1] = rb[3];
            }
            #pragma unroll
            for (int mt = 0; mt < 4; mt++)
                #pragma unroll
                for (int nt = 0; nt < 4; nt++)
                    mma_f16(acc[mt][nt], aq[mt], bq[nt]);
        }
    }

    #pragma unroll
    for (int mt = 0; mt < 4; mt++) {
        int r0 = bm + wm*64 + mt*16 + (lane >> 2);
        #pragma unroll
        for (int nt = 0; nt < 4; nt++) {
            int c0 = bn + wn*32 + nt*8 + ((lane & 3) << 1);
            *(float2*)(&C[(size_t) r0     *E_DIM + c0]) = make_float2(acc[mt][nt][0], acc[mt][nt][1]);
            *(float2*)(&C[(size_t)(r0 + 8)*E_DIM + c0]) = make_float2(acc[mt][nt][2], acc[mt][nt][3]);
        }
    }
}

// ============================================================
// 3) chunked associative exp-scan (float4 across channels)
// ============================================================
__device__ __forceinline__ void scan_step(float& a, float& b, float& p,
                                          float w, float k, float v) {
    float pw = p + w;
    float d  = pw - k;
    float e  = __expf(-fabsf(d));
    float e1 = (d >= 0.f) ? 1.f : e;
    float e2 = (d >= 0.f) ? e   : 1.f;
    a = a*e1 + v*e2;
    b = b*e1 + e2;
    p = fmaxf(pw, k);
}

__global__ void scan_pass1(const float* __restrict__ time_decay) {
    int tid = blockIdx.x * blockDim.x + threadIdx.x;
    int c = tid >> 11, ch4 = tid & (CH4 - 1);
    int ch = ch4 * 4;
    int e  = ch & (E_DIM - 1);
    float4 w4 = *(const float4*)(time_decay + e);
    float a[4] = {0.f,0.f,0.f,0.f}, b[4] = {0.f,0.f,0.f,0.f};
    float p[4] = {-1e30f,-1e30f,-1e30f,-1e30f};
    float wv[4] = {w4.x, w4.y, w4.z, w4.w};
    int base = c * CLEN;
    for (int t0 = 0; t0 < CLEN; t0 += 4) {
        float4 kk[4], vv[4];
        #pragma unroll
        for (int i = 0; i < 4; i++) {
            size_t off = (size_t)(base + t0 + i) * CH + ch;
            kk[i] = *(const float4*)(g_k + off);
            vv[i] = *(const float4*)(g_v + off);
        }
        #pragma unroll
        for (int i = 0; i < 4; i++) {
            scan_step(a[0], b[0], p[0], wv[0], kk[i].x, vv[i].x);
            scan_step(a[1], b[1], p[1], wv[1], kk[i].y, vv[i].y);
            scan_step(a[2], b[2], p[2], wv[2], kk[i].z, vv[i].z);
            scan_step(a[3], b[3], p[3], wv[3], kk[i].w, vv[i].w);
        }
    }
    *(float4*)(g_agg +               c*CH + ch) = make_float4(a[0],a[1],a[2],a[3]);
    *(float4*)(g_agg +   NCHUNK*CH + c*CH + ch) = make_float4(b[0],b[1],b[2],b[3]);
    *(float4*)(g_agg + 2*NCHUNK*CH + c*CH + ch) = make_float4(p[0],p[1],p[2],p[3]);
}

__global__ void scan_pass2(const float* __restrict__ time_decay) {
    int ch = blockIdx.x * blockDim.x + threadIdx.x;
    float w  = time_decay[ch & (E_DIM - 1)];
    float Lw = (float)CLEN * w;
    float a = 0.f, b = 0.f, p = -1e30f;
    for (int c = 0; c < NCHUNK; c++) {
        g_pre[              c*CH + ch] = a;
        g_pre[  NCHUNK*CH + c*CH + ch] = b;
        g_pre[2*NCHUNK*CH + c*CH + ch] = p;
        float a2 = g_agg[              c*CH + ch];
        float b2 = g_agg[  NCHUNK*CH + c*CH + ch];
        float p2 = g_agg[2*NCHUNK*CH + c*CH + ch];
        float pw = p + Lw;
        float d  = pw - p2;
        float e  = __expf(-fabsf(d));
        float e1 = (d >= 0.f) ? 1.f : e;
        float e2 = (d >= 0.f) ? e   : 1.f;
        a = a*e1 + a2*e2;
        b = b*e1 + b2*e2;
        p = fmaxf(pw, p2);
    }
}

__global__ void scan_pass3(const float* __restrict__ time_decay,
                           const float* __restrict__ time_first) {
    int tid = blockIdx.x * blockDim.x + threadIdx.x;
    int c = tid >> 11, ch4 = tid & (CH4 - 1);
    int ch = ch4 * 4;
    int e  = ch & (E_DIM - 1);
    float4 w4 = *(const float4*)(time_decay + e);
    float4 u4 = *(const float4*)(time_first + e);
    float wv[4] = {w4.x, w4.y, w4.z, w4.w};
    float uv[4] = {u4.x, u4.y, u4.z, u4.w};
    float4 a4 = *(const float4*)(g_pre +               c*CH + ch);
    float4 b4 = *(const float4*)(g_pre +   NCHUNK*CH + c*CH + ch);
    float4 p4 = *(const float4*)(g_pre + 2*NCHUNK*CH + c*CH + ch);
    float a[4] = {a4.x,a4.y,a4.z,a4.w};
    float b[4] = {b4.x,b4.y,b4.z,b4.w};
    float p[4] = {p4.x,p4.y,p4.z,p4.w};
    int base = c * CLEN;
    for (int t0 = 0; t0 < CLEN; t0 += 4) {
        float4 kk[4], vv[4];
        #pragma unroll
        for (int i = 0; i < 4; i++) {
            size_t off = (size_t)(base + t0 + i) * CH + ch;
            kk[i] = *(const float4*)(g_k + off);
            vv[i] = *(const float4*)(g_v + off);
        }
        #pragma unroll
        for (int i = 0; i < 4; i++) {
            float kv[4] = {kk[i].x, kk[i].y, kk[i].z, kk[i].w};
            float vvv[4] = {vv[i].x, vv[i].y, vv[i].z, vv[i].w};
            ushort4 outq;
            unsigned short qs[4];
            #pragma unroll
            for (int j = 0; j < 4; j++) {
                scan_step(a[j], b[j], p[j], wv[j], kv[j], vvv[j]);
                float kb = kv[j] + uv[j] + wv[j];
                float d2 = p[j] - kb;
                float eo = __expf(-fabsf(d2));
                float o1 = (d2 >= 0.f) ? 1.f : eo;
                float o2 = (d2 >= 0.f) ? eo  : 1.f;
                float cn = a[j]*o1 + vvv[j]*o2;
                float dn = b[j]*o1 + o2;
                qs[j] = __half_as_ushort(__float2half_rn(__fdividef(cn, dn)));
            }
            outq.x = qs[0]; outq.y = qs[1]; outq.z = qs[2]; outq.w = qs[3];
            size_t off = (size_t)(base + t0 + i) * CH + ch;
            *(ushort4*)((unsigned short*)g_r + off) = outq;
        }
    }
}

// ============================================================
// launch
// ============================================================
extern "C" void kernel_launch(void* const* d_in, const int* in_sizes, int n_in,
                              void* d_out, int out_size) {
    const float* x     = (const float*)d_in[0];
    const float* tmrkv = (const float*)d_in[1];
    const float* Wk    = (const float*)d_in[2];
    const float* Wv    = (const float*)d_in[3];
    const float* td    = (const float*)d_in[4];
    const float* tf    = (const float*)d_in[5];
    const float* Wout  = (const float*)d_in[6];
    float* out = (float*)d_out;

    cudaFuncSetAttribute(gemm_f16_1p,
                         cudaFuncAttributeMaxDynamicSharedMemorySize, GEMM_SMEM);

    __half *p_xk, *p_xv, *p_r, *p_wk, *p_wv, *p_wo;
    float *p_k, *p_v;
    cudaGetSymbolAddress((void**)&p_xk, g_xk);
    cudaGetSymbolAddress((void**)&p_xv, g_xv);
    cudaGetSymbolAddress((void**)&p_r,  g_r);
    cudaGetSymbolAddress((void**)&p_wk, g_wkt);
    cudaGetSymbolAddress((void**)&p_wv, g_wvt);
    cudaGetSymbolAddress((void**)&p_wo, g_wot);
    cudaGetSymbolAddress((void**)&p_k,  g_k);
    cudaGetSymbolAddress((void**)&p_v,  g_v);

    // 1) fused prep: mix + 3x weight transpose
    prep_kernel<<<MIXB + 3*1024, 256>>>(x, tmrkv, Wk, Wv, Wout);

    // 2) k = xk @ Wk ; v = xv @ Wv
    dim3 ggrid(E_DIM/BN, M_TOT/BM);   // (8, 64)
    gemm_f16_1p<<<ggrid, 512, GEMM_SMEM>>>(p_xk, p_wk, p_k);
    gemm_f16_1p<<<ggrid, 512, GEMM_SMEM>>>(p_xv, p_wv, p_v);

    // 3) scan
    scan_pass1<<<(NCHUNK*CH4)/256, 256>>>(td);
    scan_pass2<<<CH/256, 256>>>(td);
    scan_pass3<<<(NCHUNK*CH4)/256, 256>>>(td, tf);

    // 4) out = rwkv @ Wout
    gemm_f16_1p<<<ggrid, 512, GEMM_SMEM>>>(p_r, p_wo, out);
}

// round 11
// speedup vs baseline: 1.1588x; 1.1588x over previous
#include <cuda_runtime.h>
#include <cuda_fp16.h>
#include <cstdint>
#include <cstddef>

#define S_LEN 2048
#define B_DIM 8
#define E_DIM 1024
#define M_TOT (S_LEN*B_DIM)      // 16384
#define CH    (B_DIM*E_DIM)      // 8192
#define NCHUNK 64
#define CLEN  (S_LEN/NCHUNK)     // 32
#define CH4   (CH/4)             // 2048

// ---------------- scratch (device globals; no allocation allowed) ------------
__device__ __half g_xk[(size_t)M_TOT*E_DIM];
__device__ __half g_xv[(size_t)M_TOT*E_DIM];
__device__ __half g_r [(size_t)M_TOT*E_DIM];
__device__ float  g_k [(size_t)M_TOT*E_DIM];
__device__ __half g_vh[(size_t)M_TOT*E_DIM];
__device__ __half g_wkt[(size_t)E_DIM*E_DIM];
__device__ __half g_wvt[(size_t)E_DIM*E_DIM];
__device__ __half g_wot[(size_t)E_DIM*E_DIM];
__device__ float g_agg[3*NCHUNK*CH];
__device__ float g_pre[3*NCHUNK*CH];

// ---------------- helpers ----------------------------------------------------
__device__ __forceinline__ uint32_t smem_addr(const void* p) {
    uint32_t a;
    asm("{ .reg .u64 t; cvta.to.shared.u64 t, %1; cvt.u32.u64 %0, t; }" : "=r"(a) : "l"(p));
    return a;
}
#define CP_ASYNC16(dst, src) \
    asm volatile("cp.async.cg.shared.global [%0], [%1], 16;" :: "r"(dst), "l"(src) : "memory")
#define CP_COMMIT() asm volatile("cp.async.commit_group;" ::: "memory")
#define CP_WAIT(n)  asm volatile("cp.async.wait_group %0;" :: "n"(n) : "memory")

#define LDSM4(r, addr) \
    asm volatile("ldmatrix.sync.aligned.m8n8.x4.shared.b16 {%0,%1,%2,%3}, [%4];" \
        : "=r"((r)[0]), "=r"((r)[1]), "=r"((r)[2]), "=r"((r)[3]) : "r"(addr))

__device__ __forceinline__ void mma_f16(float c[4], const uint32_t a[4], const uint32_t b[2]) {
    asm volatile(
        "mma.sync.aligned.m16n8k16.row.col.f32.f16.f16.f32 "
        "{%0,%1,%2,%3}, {%4,%5,%6,%7}, {%8,%9}, {%0,%1,%2,%3};\n"
        : "+f"(c[0]), "+f"(c[1]), "+f"(c[2]), "+f"(c[3])
        : "r"(a[0]), "r"(a[1]), "r"(a[2]), "r"(a[3]), "r"(b[0]), "r"(b[1]));
}

// ============================================================
// 1) fused prep: token mix + fp16 quantize  AND  3x weight transpose
// ============================================================
#define MIXB (M_TOT*E_DIM/4/256)   // 16384

__global__ void prep_kernel(const float* __restrict__ x,
                            const float* __restrict__ tmrkv,
                            const float* __restrict__ Wk,
                            const float* __restrict__ Wv,
                            const float* __restrict__ Wout) {
    __shared__ float t[32][33];
    int blk = blockIdx.x;
    int tid = threadIdx.x;

    if (blk < MIXB) {
        int i4  = blk * 256 + tid;
        int idx = i4 * 4;
        int e   = idx & (E_DIM - 1);
        float4 xc = *(const float4*)(x + idx);
        float4 xp = make_float4(0.f, 0.f, 0.f, 0.f);
        if (idx >= CH) xp = *(const float4*)(x + idx - CH);
        float4 mk = *(const float4*)(tmrkv + E_DIM   + e);
        float4 mv = *(const float4*)(tmrkv + 2*E_DIM + e);
        float ok[4], ov[4];
        ok[0] = mk.x*xc.x + (1.f-mk.x)*xp.x;  ov[0] = mv.x*xc.x + (1.f-mv.x)*xp.x;
        ok[1] = mk.y*xc.y + (1.f-mk.y)*xp.y;  ov[1] = mv.y*xc.y + (1.f-mv.y)*xp.y;
        ok[2] = mk.z*xc.z + (1.f-mk.z)*xp.z;  ov[2] = mv.z*xc.z + (1.f-mv.z)*xp.z;
        ok[3] = mk.w*xc.w + (1.f-mk.w)*xp.w;  ov[3] = mv.w*xc.w + (1.f-mv.w)*xp.w;
        ushort4 kq, vq;
        kq.x = __half_as_ushort(__float2half_rn(ok[0]));
        kq.y = __half_as_ushort(__float2half_rn(ok[1]));
        kq.z = __half_as_ushort(__float2half_rn(ok[2]));
        kq.w = __half_as_ushort(__float2half_rn(ok[3]));
        vq.x = __half_as_ushort(__float2half_rn(ov[0]));
        vq.y = __half_as_ushort(__float2half_rn(ov[1]));
        vq.z = __half_as_ushort(__float2half_rn(ov[2]));
        vq.w = __half_as_ushort(__float2half_rn(ov[3]));
        *(ushort4*)((unsigned short*)g_xk + idx) = kq;
        *(ushort4*)((unsigned short*)g_xv + idx) = vq;
    } else {
        int wb   = blk - MIXB;
        int widx = wb >> 10;          // 0,1,2
        int tb   = wb & 1023;
        const float* W = (widx == 0) ? Wk : (widx == 1) ? Wv : Wout;
        __half* T = (widx == 0) ? g_wkt : (widx == 1) ? g_wvt : g_wot;
        int bx = (tb & 31) * 32;      // n block
        int by = (tb >> 5) * 32;      // k block
        int tx = tid & 31, ty = tid >> 5;   // 32 x 8
        for (int j = ty; j < 32; j += 8)
            t[j][tx] = W[(size_t)(by + j) * E_DIM + bx + tx];
        __syncthreads();
        for (int j = ty; j < 32; j += 8) {
            float v = t[tx][j];
            T[(size_t)(bx + j) * E_DIM + by + tx] = __float2half_rn(v);
        }
    }
}

// ============================================================
// 2) 1-product fp16 GEMM core (round-9 config: 128x128, 256 thr, NSTG=4)
// ============================================================
#define BM 128
#define BN 128
#define BK 32
#define TILE_B 8192
#define STAGE_B (2*TILE_B)         // 16384
#define NSTG 4
#define GEMM_SMEM (NSTG*STAGE_B)   // 65536 -> 2 CTAs/SM

// computes the 128x128 accumulator tile for (Aq, Bq) at (bm, bn)
__device__ __forceinline__ void gemm_core(const __half* __restrict__ Aq,
                                          const __half* __restrict__ Bq,
                                          int bm, int bn,
                                          uint32_t sbase, int tid,
                                          float acc[2][8][4]) {
    int warp = tid >> 5, lane = tid & 31;
    int wm = warp & 3, wn = warp >> 2;

    const char* srcs[2] = {
        (const char*)(Aq + (size_t)bm * E_DIM),
        (const char*)(Bq + (size_t)bn * E_DIM) };

    auto load_tile = [&](int kt, int stg) {
        uint32_t dst0 = sbase + (uint32_t)stg * STAGE_B;
        int koff = kt * (BK*2);
        #pragma unroll
        for (int arr = 0; arr < 2; arr++) {
            #pragma unroll
            for (int i = 0; i < 2; i++) {
                int f = tid + i*256;
                int row = f >> 2, ch = f & 3;
                int sw = ch ^ ((row >> 1) & 3);
                uint32_t dst = dst0 + arr*TILE_B + row*64 + sw*16;
                const char* src = srcs[arr] + (size_t)row * (E_DIM*2) + koff + ch*16;
                CP_ASYNC16(dst, src);
            }
        }
    };

    int lm = lane & 7, lg = lane >> 3;
    uint32_t aoff[2];
    #pragma unroll
    for (int mt = 0; mt < 2; mt++) {
        int row = wm*32 + mt*16 + (lg & 1)*8 + lm;
        int swc = (lg >> 1) ^ ((row >> 1) & 3);
        aoff[mt] = (uint32_t)(row*64 + swc*16);
    }
    uint32_t boff[4];
    #pragma unroll
    for (int j = 0; j < 4; j++) {
        int row = wn*64 + j*16 + (lg >> 1)*8 + lm;
        int swc = (lg & 1) ^ ((row >> 1) & 3);
        boff[j] = (uint32_t)(row*64 + swc*16);
    }

    const int NK = E_DIM / BK;   // 32
    load_tile(0, 0); CP_COMMIT();
    load_tile(1, 1); CP_COMMIT();
    load_tile(2, 2); CP_COMMIT();

    for (int kt = 0; kt < NK; kt++) {
        int stg = kt % NSTG;
        if (kt == NK - 1) { CP_WAIT(0); } else { CP_WAIT(2); }
        __syncthreads();
        if (kt + 3 < NK) { load_tile(kt + 3, (kt + 3) % NSTG); CP_COMMIT(); }

        uint32_t tA = sbase + (uint32_t)stg * STAGE_B;
        uint32_t tB = tA + TILE_B;

        #pragma unroll
        for (int ks = 0; ks < 2; ks++) {
            uint32_t ksx = (uint32_t)(ks * 32);
            uint32_t aq[2][4], bq[8][2];
            #pragma unroll
            for (int mt = 0; mt < 2; mt++)
                LDSM4(aq[mt], tA + (aoff[mt] ^ ksx));
            #pragma unroll
            for (int j = 0; j < 4; j++) {
                uint32_t rb[4];
                LDSM4(rb, tB + (boff[j] ^ ksx));
                bq[2*j][0] = rb[0]; bq[2*j][1] = rb[1];
                bq[2*j+1][0] = rb[2]; bq[2*j+1][1] = rb[3];
            }
            #pragma unroll
            for (int mt = 0; mt < 2; mt++)
                #pragma unroll
                for (int nt = 0; nt < 8; nt++)
                    mma_f16(acc[mt][nt], aq[mt], bq[nt]);
        }
    }
}

// fused k/v GEMM: z=0 -> k (fp32 out), z=1 -> v (fp16 out)
__global__ void __launch_bounds__(256)
gemm_kv(const __half* __restrict__ Xk, const __half* __restrict__ Wkt,
        const __half* __restrict__ Xv, const __half* __restrict__ Wvt,
        float* __restrict__ K, __half* __restrict__ V) {
    extern __shared__ uint32_t smem[];
    uint32_t sbase = smem_addr(smem);
    int tid = threadIdx.x;
    int z = blockIdx.z;
    int bm = blockIdx.y * BM, bn = blockIdx.x * BN;

    float acc[2][8][4];
    #pragma unroll
    for (int mt = 0; mt < 2; mt++)
        #pragma unroll
        for (int nt = 0; nt < 8; nt++)
            #pragma unroll
            for (int q = 0; q < 4; q++) acc[mt][nt][q] = 0.f;

    gemm_core(z ? Xv : Xk, z ? Wvt : Wkt, bm, bn, sbase, tid, acc);

    int warp = tid >> 5, lane = tid & 31;
    int wm = warp & 3, wn = warp >> 2;
    if (z == 0) {
        #pragma unroll
        for (int mt = 0; mt < 2; mt++) {
            int r0 = bm + wm*32 + mt*16 + (lane >> 2);
            #pragma unroll
            for (int nt = 0; nt < 8; nt++) {
                int c0 = bn + wn*64 + nt*8 + ((lane & 3) << 1);
                *(float2*)(&K[(size_t) r0     *E_DIM + c0]) = make_float2(acc[mt][nt][0], acc[mt][nt][1]);
                *(float2*)(&K[(size_t)(r0 + 8)*E_DIM + c0]) = make_float2(acc[mt][nt][2], acc[mt][nt][3]);
            }
        }
    } else {
        #pragma unroll
        for (int mt = 0; mt < 2; mt++) {
            int r0 = bm + wm*32 + mt*16 + (lane >> 2);
            #pragma unroll
            for (int nt = 0; nt < 8; nt++) {
                int c0 = bn + wn*64 + nt*8 + ((lane & 3) << 1);
                *(__half2*)(&V[(size_t) r0     *E_DIM + c0]) = __floats2half2_rn(acc[mt][nt][0], acc[mt][nt][1]);
                *(__half2*)(&V[(size_t)(r0 + 8)*E_DIM + c0]) = __floats2half2_rn(acc[mt][nt][2], acc[mt][nt][3]);
            }
        }
    }
}

// plain GEMM (fp32 out) for the output projection
__global__ void __launch_bounds__(256)
gemm_f16_1p(const __half* __restrict__ Aq, const __half* __restrict__ Bq,
            float* __restrict__ C) {
    extern __shared__ uint32_t smem[];
    uint32_t sbase = smem_addr(smem);
    int tid = threadIdx.x;
    int bm = blockIdx.y * BM, bn = blockIdx.x * BN;

    float acc[2][8][4];
    #pragma unroll
    for (int mt = 0; mt < 2; mt++)
        #pragma unroll
        for (int nt = 0; nt < 8; nt++)
            #pragma unroll
            for (int q = 0; q < 4; q++) acc[mt][nt][q] = 0.f;

    gemm_core(Aq, Bq, bm, bn, sbase, tid, acc);

    int warp = tid >> 5, lane = tid & 31;
    int wm = warp & 3, wn = warp >> 2;
    #pragma unroll
    for (int mt = 0; mt < 2; mt++) {
        int r0 = bm + wm*32 + mt*16 + (lane >> 2);
        #pragma unroll
        for (int nt = 0; nt < 8; nt++) {
            int c0 = bn + wn*64 + nt*8 + ((lane & 3) << 1);
            *(float2*)(&C[(size_t) r0     *E_DIM + c0]) = make_float2(acc[mt][nt][0], acc[mt][nt][1]);
            *(float2*)(&C[(size_t)(r0 + 8)*E_DIM + c0]) = make_float2(acc[mt][nt][2], acc[mt][nt][3]);
        }
    }
}

// ============================================================
// 3) chunked associative exp-scan (k fp32, v fp16)
// ============================================================
__device__ __forceinline__ void scan_step(float& a, float& b, float& p,
                                          float w, float k, float v) {
    float pw = p + w;
    float d  = pw - k;
    float e  = __expf(-fabsf(d));
    float e1 = (d >= 0.f) ? 1.f : e;
    float e2 = (d >= 0.f) ? e   : 1.f;
    a = a*e1 + v*e2;
    b = b*e1 + e2;
    p = fmaxf(pw, k);
}

__device__ __forceinline__ void load_v4(size_t off, float v[4]) {
    uint2 raw = *(const uint2*)((const unsigned short*)g_vh + off);
    float2 f01 = __half22float2(*(__half2*)&raw.x);
    float2 f23 = __half22float2(*(__half2*)&raw.y);
    v[0] = f01.x; v[1] = f01.y; v[2] = f23.x; v[3] = f23.y;
}

__global__ void scan_pass1(const float* __restrict__ time_decay) {
    int tid = blockIdx.x * blockDim.x + threadIdx.x;
    int c = tid >> 11, ch4 = tid & (CH4 - 1);
    int ch = ch4 * 4;
    int e  = ch & (E_DIM - 1);
    float4 w4 = *(const float4*)(time_decay + e);
    float a[4] = {0.f,0.f,0.f,0.f}, b[4] = {0.f,0.f,0.f,0.f};
    float p[4] = {-1e30f,-1e30f,-1e30f,-1e30f};
    float wv[4] = {w4.x, w4.y, w4.z, w4.w};
    int base = c * CLEN;
    for (int t0 = 0; t0 < CLEN; t0 += 4) {
        float4 kk[4]; float vv[4][4];
        #pragma unroll
        for (int i = 0; i < 4; i++) {
            size_t off = (size_t)(base + t0 + i) * CH + ch;
            kk[i] = *(const float4*)(g_k + off);
            load_v4(off, vv[i]);
        }
        #pragma unroll
        for (int i = 0; i < 4; i++) {
            scan_step(a[0], b[0], p[0], wv[0], kk[i].x, vv[i][0]);
            scan_step(a[1], b[1], p[1], wv[1], kk[i].y, vv[i][1]);
            scan_step(a[2], b[2], p[2], wv[2], kk[i].z, vv[i][2]);
            scan_step(a[3], b[3], p[3], wv[3], kk[i].w, vv[i][3]);
        }
    }
    *(float4*)(g_agg +               c*CH + ch) = make_float4(a[0],a[1],a[2],a[3]);
    *(float4*)(g_agg +   NCHUNK*CH + c*CH + ch) = make_float4(b[0],b[1],b[2],b[3]);
    *(float4*)(g_agg + 2*NCHUNK*CH + c*CH + ch) = make_float4(p[0],p[1],p[2],p[3]);
}

__global__ void scan_pass2(const float* __restrict__ time_decay) {
    int ch = blockIdx.x * blockDim.x + threadIdx.x;
    float w  = time_decay[ch & (E_DIM - 1)];
    float Lw = (float)CLEN * w;
    float a = 0.f, b = 0.f, p = -1e30f;
    for (int c = 0; c < NCHUNK; c++) {
        g_pre[              c*CH + ch] = a;
        g_pre[  NCHUNK*CH + c*CH + ch] = b;
        g_pre[2*NCHUNK*CH + c*CH + ch] = p;
        float a2 = g_agg[              c*CH + ch];
        float b2 = g_agg[  NCHUNK*CH + c*CH + ch];
        float p2 = g_agg[2*NCHUNK*CH + c*CH + ch];
        float pw = p + Lw;
        float d  = pw - p2;
        float e  = __expf(-fabsf(d));
        float e1 = (d >= 0.f) ? 1.f : e;
        float e2 = (d >= 0.f) ? e   : 1.f;
        a = a*e1 + a2*e2;
        b = b*e1 + b2*e2;
        p = fmaxf(pw, p2);
    }
}

__global__ void scan_pass3(const float* __restrict__ time_decay,
                           const float* __restrict__ time_first) {
    int tid = blockIdx.x * blockDim.x + threadIdx.x;
    int c = tid >> 11, ch4 = tid & (CH4 - 1);
    int ch = ch4 * 4;
    int e  = ch & (E_DIM - 1);
    float4 w4 = *(const float4*)(time_decay + e);
    float4 u4 = *(const float4*)(time_first + e);
    float wv[4] = {w4.x, w4.y, w4.z, w4.w};
    float uv[4] = {u4.x, u4.y, u4.z, u4.w};
    float4 a4 = *(const float4*)(g_pre +               c*CH + ch);
    float4 b4 = *(const float4*)(g_pre +   NCHUNK*CH + c*CH + ch);
    float4 p4 = *(const float4*)(g_pre + 2*NCHUNK*CH + c*CH + ch);
    float a[4] = {a4.x,a4.y,a4.z,a4.w};
    float b[4] = {b4.x,b4.y,b4.z,b4.w};
    float p[4] = {p4.x,p4.y,p4.z,p4.w};
    int base = c * CLEN;
    for (int t0 = 0; t0 < CLEN; t0 += 4) {
        float4 kk[4]; float vv[4][4];
        #pragma unroll
        for (int i = 0; i < 4; i++) {
            size_t off = (size_t)(base + t0 + i) * CH + ch;
            kk[i] = *(const float4*)(g_k + off);
            load_v4(off, vv[i]);
        }
        #pragma unroll
        for (int i = 0; i < 4; i++) {
            float kv[4] = {kk[i].x, kk[i].y, kk[i].z, kk[i].w};
            ushort4 outq;
            unsigned short qs[4];
            #pragma unroll
            for (int j = 0; j < 4; j++) {
                scan_step(a[j], b[j], p[j], wv[j], kv[j], vv[i][j]);
                float kb = kv[j] + uv[j] + wv[j];
                float d2 = p[j] - kb;
                float eo = __expf(-fabsf(d2));
                float o1 = (d2 >= 0.f) ? 1.f : eo;
                float o2 = (d2 >= 0.f) ? eo  : 1.f;
                float cn = a[j]*o1 + vv[i][j]*o2;
                float dn = b[j]*o1 + o2;
                qs[j] = __half_as_ushort(__float2half_rn(__fdividef(cn, dn)));
            }
            outq.x = qs[0]; outq.y = qs[1]; outq.z = qs[2]; outq.w = qs[3];
            size_t off = (size_t)(base + t0 + i) * CH + ch;
            *(ushort4*)((unsigned short*)g_r + off) = outq;
        }
    }
}

// ============================================================
// launch
// ============================================================
extern "C" void kernel_launch(void* const* d_in, const int* in_sizes, int n_in,
                              void* d_out, int out_size) {
    const float* x     = (const float*)d_in[0];
    const float* tmrkv = (const float*)d_in[1];
    const float* Wk    = (const float*)d_in[2];
    const float* Wv    = (const float*)d_in[3];
    const float* td    = (const float*)d_in[4];
    const float* tf    = (const float*)d_in[5];
    const float* Wout  = (const float*)d_in[6];
    float* out = (float*)d_out;

    cudaFuncSetAttribute(gemm_kv,
                         cudaFuncAttributeMaxDynamicSharedMemorySize, GEMM_SMEM);
    cudaFuncSetAttribute(gemm_f16_1p,
                         cudaFuncAttributeMaxDynamicSharedMemorySize, GEMM_SMEM);

    __half *p_xk, *p_xv, *p_r, *p_wk, *p_wv, *p_wo, *p_vh;
    float *p_k;
    cudaGetSymbolAddress((void**)&p_xk, g_xk);
    cudaGetSymbolAddress((void**)&p_xv, g_xv);
    cudaGetSymbolAddress((void**)&p_r,  g_r);
    cudaGetSymbolAddress((void**)&p_wk, g_wkt);
    cudaGetSymbolAddress((void**)&p_wv, g_wvt);
    cudaGetSymbolAddress((void**)&p_wo, g_wot);
    cudaGetSymbolAddress((void**)&p_k,  g_k);
    cudaGetSymbolAddress((void**)&p_vh, g_vh);

    // 1) fused prep: mix + 3x weight transpose
    prep_kernel<<<MIXB + 3*1024, 256>>>(x, tmrkv, Wk, Wv, Wout);

    // 2) fused k/v GEMM
    dim3 kvgrid(E_DIM/BN, M_TOT/BM, 2);   // (8, 128, 2)
    gemm_kv<<<kvgrid, 256, GEMM_SMEM>>>(p_xk, p_wk, p_xv, p_wv, p_k, p_vh);

    // 3) scan
    scan_pass1<<<(NCHUNK*CH4)/256, 256>>>(td);
    scan_pass2<<<CH/256, 256>>>(td);
    scan_pass3<<<(NCHUNK*CH4)/256, 256>>>(td, tf);

    // 4) out = rwkv @ Wout
    dim3 ggrid(E_DIM/BN, M_TOT/BM);
    gemm_f16_1p<<<ggrid, 256, GEMM_SMEM>>>(p_r, p_wo, out);
}

// round 12
// speedup vs baseline: 1.1715x; 1.0110x over previous
#include <cuda_runtime.h>
#include <cuda_fp16.h>
#include <cstdint>
#include <cstddef>

#define S_LEN 2048
#define B_DIM 8
#define E_DIM 1024
#define M_TOT (S_LEN*B_DIM)      // 16384
#define CH    (B_DIM*E_DIM)      // 8192
#define NCHUNK 64
#define CLEN  (S_LEN/NCHUNK)     // 32
#define CH4   (CH/4)             // 2048

// ---------------- scratch (device globals; no allocation allowed) ------------
__device__ __half g_xk[(size_t)M_TOT*E_DIM];
__device__ __half g_xv[(size_t)M_TOT*E_DIM];
__device__ __half g_r [(size_t)M_TOT*E_DIM];
__device__ float  g_k [(size_t)M_TOT*E_DIM];
__device__ __half g_vh[(size_t)M_TOT*E_DIM];
__device__ __half g_wkt[(size_t)E_DIM*E_DIM];
__device__ __half g_wvt[(size_t)E_DIM*E_DIM];
__device__ __half g_wot[(size_t)E_DIM*E_DIM];
__device__ float g_agg[3*NCHUNK*CH];
__device__ float g_pre[3*NCHUNK*CH];

// ---------------- helpers ----------------------------------------------------
__device__ __forceinline__ uint32_t smem_addr(const void* p) {
    uint32_t a;
    asm("{ .reg .u64 t; cvta.to.shared.u64 t, %1; cvt.u32.u64 %0, t; }" : "=r"(a) : "l"(p));
    return a;
}
#define CP_ASYNC16(dst, src) \
    asm volatile("cp.async.cg.shared.global [%0], [%1], 16;" :: "r"(dst), "l"(src) : "memory")
#define CP_COMMIT() asm volatile("cp.async.commit_group;" ::: "memory")
#define CP_WAIT(n)  asm volatile("cp.async.wait_group %0;" :: "n"(n) : "memory")

#define LDSM4(r, addr) \
    asm volatile("ldmatrix.sync.aligned.m8n8.x4.shared.b16 {%0,%1,%2,%3}, [%4];" \
        : "=r"((r)[0]), "=r"((r)[1]), "=r"((r)[2]), "=r"((r)[3]) : "r"(addr))

__device__ __forceinline__ void mma_f16(float c[4], const uint32_t a[4], const uint32_t b[2]) {
    asm volatile(
        "mma.sync.aligned.m16n8k16.row.col.f32.f16.f16.f32 "
        "{%0,%1,%2,%3}, {%4,%5,%6,%7}, {%8,%9}, {%0,%1,%2,%3};\n"
        : "+f"(c[0]), "+f"(c[1]), "+f"(c[2]), "+f"(c[3])
        : "r"(a[0]), "r"(a[1]), "r"(a[2]), "r"(a[3]), "r"(b[0]), "r"(b[1]));
}

// ============================================================
// 1) fused prep: token mix + fp16 quantize  AND  3x weight transpose
// ============================================================
#define MIXB (M_TOT*E_DIM/4/256)   // 16384

__global__ void prep_kernel(const float* __restrict__ x,
                            const float* __restrict__ tmrkv,
                            const float* __restrict__ Wk,
                            const float* __restrict__ Wv,
                            const float* __restrict__ Wout) {
    __shared__ float t[32][33];
    int blk = blockIdx.x;
    int tid = threadIdx.x;

    if (blk < MIXB) {
        int i4  = blk * 256 + tid;
        int idx = i4 * 4;
        int e   = idx & (E_DIM - 1);
        float4 xc = *(const float4*)(x + idx);
        float4 xp = make_float4(0.f, 0.f, 0.f, 0.f);
        if (idx >= CH) xp = *(const float4*)(x + idx - CH);
        float4 mk = *(const float4*)(tmrkv + E_DIM   + e);
        float4 mv = *(const float4*)(tmrkv + 2*E_DIM + e);
        float ok[4], ov[4];
        ok[0] = mk.x*xc.x + (1.f-mk.x)*xp.x;  ov[0] = mv.x*xc.x + (1.f-mv.x)*xp.x;
        ok[1] = mk.y*xc.y + (1.f-mk.y)*xp.y;  ov[1] = mv.y*xc.y + (1.f-mv.y)*xp.y;
        ok[2] = mk.z*xc.z + (1.f-mk.z)*xp.z;  ov[2] = mv.z*xc.z + (1.f-mv.z)*xp.z;
        ok[3] = mk.w*xc.w + (1.f-mk.w)*xp.w;  ov[3] = mv.w*xc.w + (1.f-mv.w)*xp.w;
        ushort4 kq, vq;
        kq.x = __half_as_ushort(__float2half_rn(ok[0]));
        kq.y = __half_as_ushort(__float2half_rn(ok[1]));
        kq.z = __half_as_ushort(__float2half_rn(ok[2]));
        kq.w = __half_as_ushort(__float2half_rn(ok[3]));
        vq.x = __half_as_ushort(__float2half_rn(ov[0]));
        vq.y = __half_as_ushort(__float2half_rn(ov[1]));
        vq.z = __half_as_ushort(__float2half_rn(ov[2]));
        vq.w = __half_as_ushort(__float2half_rn(ov[3]));
        *(ushort4*)((unsigned short*)g_xk + idx) = kq;
        *(ushort4*)((unsigned short*)g_xv + idx) = vq;
    } else {
        int wb   = blk - MIXB;
        int widx = wb >> 10;          // 0,1,2
        int tb   = wb & 1023;
        const float* W = (widx == 0) ? Wk : (widx == 1) ? Wv : Wout;
        __half* T = (widx == 0) ? g_wkt : (widx == 1) ? g_wvt : g_wot;
        int bx = (tb & 31) * 32;      // n block
        int by = (tb >> 5) * 32;      // k block
        int tx = tid & 31, ty = tid >> 5;   // 32 x 8
        for (int j = ty; j < 32; j += 8)
            t[j][tx] = W[(size_t)(by + j) * E_DIM + bx + tx];
        __syncthreads();
        for (int j = ty; j < 32; j += 8) {
            float v = t[tx][j];
            T[(size_t)(bx + j) * E_DIM + by + tx] = __float2half_rn(v);
        }
    }
}

// ============================================================
// 2) 1-product fp16 GEMM core (128x128, 256 thr, NSTG=4)
// ============================================================
#define BM 128
#define BN 128
#define BK 32
#define TILE_B 8192
#define STAGE_B (2*TILE_B)         // 16384
#define NSTG 4
#define GEMM_SMEM (NSTG*STAGE_B)   // 65536 -> 2 CTAs/SM

__device__ __forceinline__ void gemm_core(const __half* __restrict__ Aq,
                                          const __half* __restrict__ Bq,
                                          int bm, int bn,
                                          uint32_t sbase, int tid,
                                          float acc[2][8][4]) {
    int warp = tid >> 5, lane = tid & 31;
    int wm = warp & 3, wn = warp >> 2;

    const char* srcs[2] = {
        (const char*)(Aq + (size_t)bm * E_DIM),
        (const char*)(Bq + (size_t)bn * E_DIM) };

    auto load_tile = [&](int kt, int stg) {
        uint32_t dst0 = sbase + (uint32_t)stg * STAGE_B;
        int koff = kt * (BK*2);
        #pragma unroll
        for (int arr = 0; arr < 2; arr++) {
            #pragma unroll
            for (int i = 0; i < 2; i++) {
                int f = tid + i*256;
                int row = f >> 2, ch = f & 3;
                int sw = ch ^ ((row >> 1) & 3);
                uint32_t dst = dst0 + arr*TILE_B + row*64 + sw*16;
                const char* src = srcs[arr] + (size_t)row * (E_DIM*2) + koff + ch*16;
                CP_ASYNC16(dst, src);
            }
        }
    };

    int lm = lane & 7, lg = lane >> 3;
    uint32_t aoff[2];
    #pragma unroll
    for (int mt = 0; mt < 2; mt++) {
        int row = wm*32 + mt*16 + (lg & 1)*8 + lm;
        int swc = (lg >> 1) ^ ((row >> 1) & 3);
        aoff[mt] = (uint32_t)(row*64 + swc*16);
    }
    uint32_t boff[4];
    #pragma unroll
    for (int j = 0; j < 4; j++) {
        int row = wn*64 + j*16 + (lg >> 1)*8 + lm;
        int swc = (lg & 1) ^ ((row >> 1) & 3);
        boff[j] = (uint32_t)(row*64 + swc*16);
    }

    const int NK = E_DIM / BK;   // 32
    load_tile(0, 0); CP_COMMIT();
    load_tile(1, 1); CP_COMMIT();
    load_tile(2, 2); CP_COMMIT();

    for (int kt = 0; kt < NK; kt++) {
        int stg = kt % NSTG;
        if (kt == NK - 1) { CP_WAIT(0); } else { CP_WAIT(2); }
        __syncthreads();
        if (kt + 3 < NK) { load_tile(kt + 3, (kt + 3) % NSTG); CP_COMMIT(); }

        uint32_t tA = sbase + (uint32_t)stg * STAGE_B;
        uint32_t tB = tA + TILE_B;

        #pragma unroll
        for (int ks = 0; ks < 2; ks++) {
            uint32_t ksx = (uint32_t)(ks * 32);
            uint32_t aq[2][4], bq[8][2];
            #pragma unroll
            for (int mt = 0; mt < 2; mt++)
                LDSM4(aq[mt], tA + (aoff[mt] ^ ksx));
            #pragma unroll
            for (int j = 0; j < 4; j++) {
                uint32_t rb[4];
                LDSM4(rb, tB + (boff[j] ^ ksx));
                bq[2*j][0] = rb[0]; bq[2*j][1] = rb[1];
                bq[2*j+1][0] = rb[2]; bq[2*j+1][1] = rb[3];
            }
            #pragma unroll
            for (int mt = 0; mt < 2; mt++)
                #pragma unroll
                for (int nt = 0; nt < 8; nt++)
                    mma_f16(acc[mt][nt], aq[mt], bq[nt]);
        }
    }
}

// fused k/v GEMM: z=0 -> k (fp32 out), z=1 -> v (fp16 out)
__global__ void __launch_bounds__(256)
gemm_kv(const __half* __restrict__ Xk, const __half* __restrict__ Wkt,
        const __half* __restrict__ Xv, const __half* __restrict__ Wvt,
        float* __restrict__ K, __half* __restrict__ V) {
    extern __shared__ uint32_t smem[];
    uint32_t sbase = smem_addr(smem);
    int tid = threadIdx.x;
    int z = blockIdx.z;
    int bm = blockIdx.y * BM, bn = blockIdx.x * BN;

    float acc[2][8][4];
    #pragma unroll
    for (int mt = 0; mt < 2; mt++)
        #pragma unroll
        for (int nt = 0; nt < 8; nt++)
            #pragma unroll
            for (int q = 0; q < 4; q++) acc[mt][nt][q] = 0.f;

    gemm_core(z ? Xv : Xk, z ? Wvt : Wkt, bm, bn, sbase, tid, acc);

    int warp = tid >> 5, lane = tid & 31;
    int wm = warp & 3, wn = warp >> 2;
    if (z == 0) {
        #pragma unroll
        for (int mt = 0; mt < 2; mt++) {
            int r0 = bm + wm*32 + mt*16 + (lane >> 2);
            #pragma unroll
            for (int nt = 0; nt < 8; nt++) {
                int c0 = bn + wn*64 + nt*8 + ((lane & 3) << 1);
                *(float2*)(&K[(size_t) r0     *E_DIM + c0]) = make_float2(acc[mt][nt][0], acc[mt][nt][1]);
                *(float2*)(&K[(size_t)(r0 + 8)*E_DIM + c0]) = make_float2(acc[mt][nt][2], acc[mt][nt][3]);
            }
        }
    } else {
        #pragma unroll
        for (int mt = 0; mt < 2; mt++) {
            int r0 = bm + wm*32 + mt*16 + (lane >> 2);
            #pragma unroll
            for (int nt = 0; nt < 8; nt++) {
                int c0 = bn + wn*64 + nt*8 + ((lane & 3) << 1);
                *(__half2*)(&V[(size_t) r0     *E_DIM + c0]) = __floats2half2_rn(acc[mt][nt][0], acc[mt][nt][1]);
                *(__half2*)(&V[(size_t)(r0 + 8)*E_DIM + c0]) = __floats2half2_rn(acc[mt][nt][2], acc[mt][nt][3]);
            }
        }
    }
}

// plain GEMM (fp32 out) for the output projection
__global__ void __launch_bounds__(256)
gemm_f16_1p(const __half* __restrict__ Aq, const __half* __restrict__ Bq,
            float* __restrict__ C) {
    extern __shared__ uint32_t smem[];
    uint32_t sbase = smem_addr(smem);
    int tid = threadIdx.x;
    int bm = blockIdx.y * BM, bn = blockIdx.x * BN;

    float acc[2][8][4];
    #pragma unroll
    for (int mt = 0; mt < 2; mt++)
        #pragma unroll
        for (int nt = 0; nt < 8; nt++)
            #pragma unroll
            for (int q = 0; q < 4; q++) acc[mt][nt][q] = 0.f;

    gemm_core(Aq, Bq, bm, bn, sbase, tid, acc);

    int warp = tid >> 5, lane = tid & 31;
    int wm = warp & 3, wn = warp >> 2;
    #pragma unroll
    for (int mt = 0; mt < 2; mt++) {
        int r0 = bm + wm*32 + mt*16 + (lane >> 2);
        #pragma unroll
        for (int nt = 0; nt < 8; nt++) {
            int c0 = bn + wn*64 + nt*8 + ((lane & 3) << 1);
            *(float2*)(&C[(size_t) r0     *E_DIM + c0]) = make_float2(acc[mt][nt][0], acc[mt][nt][1]);
            *(float2*)(&C[(size_t)(r0 + 8)*E_DIM + c0]) = make_float2(acc[mt][nt][2], acc[mt][nt][3]);
        }
    }
}

// ============================================================
// 3) chunked associative exp-scan (k fp32, v fp16)
// ============================================================
__device__ __forceinline__ void scan_step(float& a, float& b, float& p,
                                          float w, float k, float v) {
    float pw = p + w;
    float d  = pw - k;
    float e  = __expf(-fabsf(d));
    float e1 = (d >= 0.f) ? 1.f : e;
    float e2 = (d >= 0.f) ? e   : 1.f;
    a = a*e1 + v*e2;
    b = b*e1 + e2;
    p = fmaxf(pw, k);
}

// combine(left,(aL,bL,pL), right=(a,b,p) covering `cw` chunks): decay left by cw*Lw
__device__ __forceinline__ void seg_combine(float aL, float bL, float pL,
                                            float& a, float& b, float& p,
                                            float cwLw) {
    float pw = pL + cwLw;
    float d  = pw - p;
    float e  = __expf(-fabsf(d));
    float e1 = (d >= 0.f) ? 1.f : e;
    float e2 = (d >= 0.f) ? e   : 1.f;
    a = aL*e1 + a*e2;
    b = bL*e1 + b*e2;
    p = fmaxf(pw, p);
}

__device__ __forceinline__ void load_v4(size_t off, float v[4]) {
    uint2 raw = *(const uint2*)((const unsigned short*)g_vh + off);
    float2 f01 = __half22float2(*(__half2*)&raw.x);
    float2 f23 = __half22float2(*(__half2*)&raw.y);
    v[0] = f01.x; v[1] = f01.y; v[2] = f23.x; v[3] = f23.y;
}

__global__ void scan_pass1(const float* __restrict__ time_decay) {
    int tid = blockIdx.x * blockDim.x + threadIdx.x;
    int c = tid >> 11, ch4 = tid & (CH4 - 1);
    int ch = ch4 * 4;
    int e  = ch & (E_DIM - 1);
    float4 w4 = *(const float4*)(time_decay + e);
    float a[4] = {0.f,0.f,0.f,0.f}, b[4] = {0.f,0.f,0.f,0.f};
    float p[4] = {-1e30f,-1e30f,-1e30f,-1e30f};
    float wv[4] = {w4.x, w4.y, w4.z, w4.w};
    int base = c * CLEN;
    for (int t0 = 0; t0 < CLEN; t0 += 4) {
        float4 kk[4]; float vv[4][4];
        #pragma unroll
        for (int i = 0; i < 4; i++) {
            size_t off = (size_t)(base + t0 + i) * CH + ch;
            kk[i] = *(const float4*)(g_k + off);
            load_v4(off, vv[i]);
        }
        #pragma unroll
        for (int i = 0; i < 4; i++) {
            scan_step(a[0], b[0], p[0], wv[0], kk[i].x, vv[i][0]);
            scan_step(a[1], b[1], p[1], wv[1], kk[i].y, vv[i][1]);
            scan_step(a[2], b[2], p[2], wv[2], kk[i].z, vv[i][2]);
            scan_step(a[3], b[3], p[3], wv[3], kk[i].w, vv[i][3]);
        }
    }
    *(float4*)(g_agg +               c*CH + ch) = make_float4(a[0],a[1],a[2],a[3]);
    *(float4*)(g_agg +   NCHUNK*CH + c*CH + ch) = make_float4(b[0],b[1],b[2],b[3]);
    *(float4*)(g_agg + 2*NCHUNK*CH + c*CH + ch) = make_float4(p[0],p[1],p[2],p[3]);
}

// warp-parallel exclusive scan over NCHUNK=64 chunks: 1 warp per channel,
// 2 chunks per lane, Kogge-Stone over 32 lane-segments.
__global__ void scan_pass2(const float* __restrict__ time_decay) {
    int gwarp = (blockIdx.x * blockDim.x + threadIdx.x) >> 5;  // channel
    int lane  = threadIdx.x & 31;
    int ch = gwarp;
    float w  = time_decay[ch & (E_DIM - 1)];
    float Lw = (float)CLEN * w;

    int c0 = lane * 2, c1 = c0 + 1;
    float a0 = g_agg[              c0*CH + ch];
    float b0 = g_agg[  NCHUNK*CH + c0*CH + ch];
    float p0 = g_agg[2*NCHUNK*CH + c0*CH + ch];
    float a  = g_agg[              c1*CH + ch];
    float b  = g_agg[  NCHUNK*CH + c1*CH + ch];
    float p  = g_agg[2*NCHUNK*CH + c1*CH + ch];

    // pair combine: (a,b,p) <- combine(chunk c0, chunk c1), covers 2 chunks
    seg_combine(a0, b0, p0, a, b, p, Lw);
    int cnt = 2;

    // inclusive Kogge-Stone over lanes
    #pragma unroll
    for (int d = 1; d < 32; d <<= 1) {
        float aL = __shfl_up_sync(0xffffffffu, a, d);
        float bL = __shfl_up_sync(0xffffffffu, b, d);
        float pL = __shfl_up_sync(0xffffffffu, p, d);
        int   cL = __shfl_up_sync(0xffffffffu, cnt, d);
        if (lane >= d) {
            seg_combine(aL, bL, pL, a, b, p, (float)cnt * Lw);
            cnt += cL;
        }
    }

    // exclusive prefix for this lane's segment
    float ae = __shfl_up_sync(0xffffffffu, a, 1);
    float be = __shfl_up_sync(0xffffffffu, b, 1);
    float pe = __shfl_up_sync(0xffffffffu, p, 1);
    if (lane == 0) { ae = 0.f; be = 0.f; pe = -1e30f; }

    // prefix before c0
    g_pre[              c0*CH + ch] = ae;
    g_pre[  NCHUNK*CH + c0*CH + ch] = be;
    g_pre[2*NCHUNK*CH + c0*CH + ch] = pe;
    // prefix before c1 = combine(excl, chunk c0)
    seg_combine(ae, be, pe, a0, b0, p0, Lw);
    g_pre[              c1*CH + ch] = a0;
    g_pre[  NCHUNK*CH + c1*CH + ch] = b0;
    g_pre[2*NCHUNK*CH + c1*CH + ch] = p0;
}

__global__ void scan_pass3(const float* __restrict__ time_decay,
                           const float* __restrict__ time_first) {
    int tid = blockIdx.x * blockDim.x + threadIdx.x;
    int c = tid >> 11, ch4 = tid & (CH4 - 1);
    int ch = ch4 * 4;
    int e  = ch & (E_DIM - 1);
    float4 w4 = *(const float4*)(time_decay + e);
    float4 u4 = *(const float4*)(time_first + e);
    float wv[4] = {w4.x, w4.y, w4.z, w4.w};
    float uv[4] = {u4.x, u4.y, u4.z, u4.w};
    float4 a4 = *(const float4*)(g_pre +               c*CH + ch);
    float4 b4 = *(const float4*)(g_pre +   NCHUNK*CH + c*CH + ch);
    float4 p4 = *(const float4*)(g_pre + 2*NCHUNK*CH + c*CH + ch);
    float a[4] = {a4.x,a4.y,a4.z,a4.w};
    float b[4] = {b4.x,b4.y,b4.z,b4.w};
    float p[4] = {p4.x,p4.y,p4.z,p4.w};
    int base = c * CLEN;
    for (int t0 = 0; t0 < CLEN; t0 += 4) {
        float4 kk[4]; float vv[4][4];
        #pragma unroll
        for (int i = 0; i < 4; i++) {
            size_t off = (size_t)(base + t0 + i) * CH + ch;
            kk[i] = *(const float4*)(g_k + off);
            load_v4(off, vv[i]);
        }
        #pragma unroll
        for (int i = 0; i < 4; i++) {
            float kv[4] = {kk[i].x, kk[i].y, kk[i].z, kk[i].w};
            ushort4 outq;
            unsigned short qs[4];
            #pragma unroll
            for (int j = 0; j < 4; j++) {
                scan_step(a[j], b[j], p[j], wv[j], kv[j], vv[i][j]);
                float kb = kv[j] + uv[j] + wv[j];
                float d2 = p[j] - kb;
                float eo = __expf(-fabsf(d2));
                float o1 = (d2 >= 0.f) ? 1.f : eo;
                float o2 = (d2 >= 0.f) ? eo  : 1.f;
                float cn = a[j]*o1 + vv[i][j]*o2;
                float dn = b[j]*o1 + o2;
                qs[j] = __half_as_ushort(__float2half_rn(__fdividef(cn, dn)));
            }
            outq.x = qs[0]; outq.y = qs[1]; outq.z = qs[2]; outq.w = qs[3];
            size_t off = (size_t)(base + t0 + i) * CH + ch;
            *(ushort4*)((unsigned short*)g_r + off) = outq;
        }
    }
}

// ============================================================
// launch
// ============================================================
extern "C" void kernel_launch(void* const* d_in, const int* in_sizes, int n_in,
                              void* d_out, int out_size) {
    const float* x     = (const float*)d_in[0];
    const float* tmrkv = (const float*)d_in[1];
    const float* Wk    = (const float*)d_in[2];
    const float* Wv    = (const float*)d_in[3];
    const float* td    = (const float*)d_in[4];
    const float* tf    = (const float*)d_in[5];
    const float* Wout  = (const float*)d_in[6];
    float* out = (float*)d_out;

    cudaFuncSetAttribute(gemm_kv,
                         cudaFuncAttributeMaxDynamicSharedMemorySize, GEMM_SMEM);
    cudaFuncSetAttribute(gemm_f16_1p,
                         cudaFuncAttributeMaxDynamicSharedMemorySize, GEMM_SMEM);

    __half *p_xk, *p_xv, *p_r, *p_wk, *p_wv, *p_wo, *p_vh;
    float *p_k;
    cudaGetSymbolAddress((void**)&p_xk, g_xk);
    cudaGetSymbolAddress((void**)&p_xv, g_xv);
    cudaGetSymbolAddress((void**)&p_r,  g_r);
    cudaGetSymbolAddress((void**)&p_wk, g_wkt);
    cudaGetSymbolAddress((void**)&p_wv, g_wvt);
    cudaGetSymbolAddress((void**)&p_wo, g_wot);
    cudaGetSymbolAddress((void**)&p_k,  g_k);
    cudaGetSymbolAddress((void**)&p_vh, g_vh);

    // 1) fused prep: mix + 3x weight transpose
    prep_kernel<<<MIXB + 3*1024, 256>>>(x, tmrkv, Wk, Wv, Wout);

    // 2) fused k/v GEMM
    dim3 kvgrid(E_DIM/BN, M_TOT/BM, 2);   // (8, 128, 2)
    gemm_kv<<<kvgrid, 256, GEMM_SMEM>>>(p_xk, p_wk, p_xv, p_wv, p_k, p_vh);

    // 3) scan: pass2 is warp-parallel (1 warp/channel -> 8192 warps)
    scan_pass1<<<(NCHUNK*CH4)/256, 256>>>(td);
    scan_pass2<<<(CH*32)/256, 256>>>(td);
    scan_pass3<<<(NCHUNK*CH4)/256, 256>>>(td, tf);

    // 4) out = rwkv @ Wout
    dim3 ggrid(E_DIM/BN, M_TOT/BM);
    gemm_f16_1p<<<ggrid, 256, GEMM_SMEM>>>(p_r, p_wo, out);
}

// round 13
// speedup vs baseline: 1.1938x; 1.0191x over previous
#include <cuda_runtime.h>
#include <cuda_fp16.h>
#include <cstdint>
#include <cstddef>

#define S_LEN 2048
#define B_DIM 8
#define E_DIM 1024
#define M_TOT (S_LEN*B_DIM)      // 16384
#define CH    (B_DIM*E_DIM)      // 8192
#define NCHUNK 128
#define CLEN  (S_LEN/NCHUNK)     // 16
#define CH4   (CH/4)             // 2048

// ---------------- scratch (device globals; no allocation allowed) ------------
__device__ __half g_xk[(size_t)M_TOT*E_DIM];
__device__ __half g_xv[(size_t)M_TOT*E_DIM];
__device__ __half g_r [(size_t)M_TOT*E_DIM];
__device__ float  g_k [(size_t)M_TOT*E_DIM];
__device__ __half g_vh[(size_t)M_TOT*E_DIM];
__device__ __half g_wkt[(size_t)E_DIM*E_DIM];
__device__ __half g_wvt[(size_t)E_DIM*E_DIM];
__device__ __half g_wot[(size_t)E_DIM*E_DIM];
__device__ float g_agg[3*NCHUNK*CH];
__device__ float g_pre[3*NCHUNK*CH];

// ---------------- helpers ----------------------------------------------------
__device__ __forceinline__ uint32_t smem_addr(const void* p) {
    uint32_t a;
    asm("{ .reg .u64 t; cvta.to.shared.u64 t, %1; cvt.u32.u64 %0, t; }" : "=r"(a) : "l"(p));
    return a;
}
#define CP_ASYNC16(dst, src) \
    asm volatile("cp.async.cg.shared.global [%0], [%1], 16;" :: "r"(dst), "l"(src) : "memory")
#define CP_COMMIT() asm volatile("cp.async.commit_group;" ::: "memory")
#define CP_WAIT(n)  asm volatile("cp.async.wait_group %0;" :: "n"(n) : "memory")

#define LDSM4(r, addr) \
    asm volatile("ldmatrix.sync.aligned.m8n8.x4.shared.b16 {%0,%1,%2,%3}, [%4];" \
        : "=r"((r)[0]), "=r"((r)[1]), "=r"((r)[2]), "=r"((r)[3]) : "r"(addr))

__device__ __forceinline__ void mma_f16(float c[4], const uint32_t a[4], const uint32_t b[2]) {
    asm volatile(
        "mma.sync.aligned.m16n8k16.row.col.f32.f16.f16.f32 "
        "{%0,%1,%2,%3}, {%4,%5,%6,%7}, {%8,%9}, {%0,%1,%2,%3};\n"
        : "+f"(c[0]), "+f"(c[1]), "+f"(c[2]), "+f"(c[3])
        : "r"(a[0]), "r"(a[1]), "r"(a[2]), "r"(a[3]), "r"(b[0]), "r"(b[1]));
}

// ============================================================
// 1) fused prep: token mix + fp16 quantize  AND  3x weight transpose
// ============================================================
#define MIXB (M_TOT*E_DIM/4/256)   // 16384

__global__ void prep_kernel(const float* __restrict__ x,
                            const float* __restrict__ tmrkv,
                            const float* __restrict__ Wk,
                            const float* __restrict__ Wv,
                            const float* __restrict__ Wout) {
    __shared__ float t[32][33];
    int blk = blockIdx.x;
    int tid = threadIdx.x;

    if (blk < MIXB) {
        int i4  = blk * 256 + tid;
        int idx = i4 * 4;
        int e   = idx & (E_DIM - 1);
        float4 xc = *(const float4*)(x + idx);
        float4 xp = make_float4(0.f, 0.f, 0.f, 0.f);
        if (idx >= CH) xp = *(const float4*)(x + idx - CH);
        float4 mk = *(const float4*)(tmrkv + E_DIM   + e);
        float4 mv = *(const float4*)(tmrkv + 2*E_DIM + e);
        float ok[4], ov[4];
        ok[0] = mk.x*xc.x + (1.f-mk.x)*xp.x;  ov[0] = mv.x*xc.x + (1.f-mv.x)*xp.x;
        ok[1] = mk.y*xc.y + (1.f-mk.y)*xp.y;  ov[1] = mv.y*xc.y + (1.f-mv.y)*xp.y;
        ok[2] = mk.z*xc.z + (1.f-mk.z)*xp.z;  ov[2] = mv.z*xc.z + (1.f-mv.z)*xp.z;
        ok[3] = mk.w*xc.w + (1.f-mk.w)*xp.w;  ov[3] = mv.w*xc.w + (1.f-mv.w)*xp.w;
        ushort4 kq, vq;
        kq.x = __half_as_ushort(__float2half_rn(ok[0]));
        kq.y = __half_as_ushort(__float2half_rn(ok[1]));
        kq.z = __half_as_ushort(__float2half_rn(ok[2]));
        kq.w = __half_as_ushort(__float2half_rn(ok[3]));
        vq.x = __half_as_ushort(__float2half_rn(ov[0]));
        vq.y = __half_as_ushort(__float2half_rn(ov[1]));
        vq.z = __half_as_ushort(__float2half_rn(ov[2]));
        vq.w = __half_as_ushort(__float2half_rn(ov[3]));
        *(ushort4*)((unsigned short*)g_xk + idx) = kq;
        *(ushort4*)((unsigned short*)g_xv + idx) = vq;
    } else {
        int wb   = blk - MIXB;
        int widx = wb >> 10;          // 0,1,2
        int tb   = wb & 1023;
        const float* W = (widx == 0) ? Wk : (widx == 1) ? Wv : Wout;
        __half* T = (widx == 0) ? g_wkt : (widx == 1) ? g_wvt : g_wot;
        int bx = (tb & 31) * 32;      // n block
        int by = (tb >> 5) * 32;      // k block
        int tx = tid & 31, ty = tid >> 5;   // 32 x 8
        for (int j = ty; j < 32; j += 8)
            t[j][tx] = W[(size_t)(by + j) * E_DIM + bx + tx];
        __syncthreads();
        for (int j = ty; j < 32; j += 8) {
            float v = t[tx][j];
            T[(size_t)(bx + j) * E_DIM + by + tx] = __float2half_rn(v);
        }
    }
}

// ============================================================
// 2) 1-product fp16 GEMM core (128x128, 256 thr, NSTG=4)
// ============================================================
#define BM 128
#define BN 128
#define BK 32
#define TILE_B 8192
#define STAGE_B (2*TILE_B)         // 16384
#define NSTG 4
#define GEMM_SMEM (NSTG*STAGE_B)   // 65536 -> 2 CTAs/SM

__device__ __forceinline__ void gemm_core(const __half* __restrict__ Aq,
                                          const __half* __restrict__ Bq,
                                          int bm, int bn,
                                          uint32_t sbase, int tid,
                                          float acc[2][8][4]) {
    int warp = tid >> 5, lane = tid & 31;
    int wm = warp & 3, wn = warp >> 2;

    const char* srcs[2] = {
        (const char*)(Aq + (size_t)bm * E_DIM),
        (const char*)(Bq + (size_t)bn * E_DIM) };

    auto load_tile = [&](int kt, int stg) {
        uint32_t dst0 = sbase + (uint32_t)stg * STAGE_B;
        int koff = kt * (BK*2);
        #pragma unroll
        for (int arr = 0; arr < 2; arr++) {
            #pragma unroll
            for (int i = 0; i < 2; i++) {
                int f = tid + i*256;
                int row = f >> 2, ch = f & 3;
                int sw = ch ^ ((row >> 1) & 3);
                uint32_t dst = dst0 + arr*TILE_B + row*64 + sw*16;
                const char* src = srcs[arr] + (size_t)row * (E_DIM*2) + koff + ch*16;
                CP_ASYNC16(dst, src);
            }
        }
    };

    int lm = lane & 7, lg = lane >> 3;
    uint32_t aoff[2];
    #pragma unroll
    for (int mt = 0; mt < 2; mt++) {
        int row = wm*32 + mt*16 + (lg & 1)*8 + lm;
        int swc = (lg >> 1) ^ ((row >> 1) & 3);
        aoff[mt] = (uint32_t)(row*64 + swc*16);
    }
    uint32_t boff[4];
    #pragma unroll
    for (int j = 0; j < 4; j++) {
        int row = wn*64 + j*16 + (lg >> 1)*8 + lm;
        int swc = (lg & 1) ^ ((row >> 1) & 3);
        boff[j] = (uint32_t)(row*64 + swc*16);
    }

    const int NK = E_DIM / BK;   // 32
    load_tile(0, 0); CP_COMMIT();
    load_tile(1, 1); CP_COMMIT();
    load_tile(2, 2); CP_COMMIT();

    for (int kt = 0; kt < NK; kt++) {
        int stg = kt % NSTG;
        if (kt == NK - 1) { CP_WAIT(0); } else { CP_WAIT(2); }
        __syncthreads();
        if (kt + 3 < NK) { load_tile(kt + 3, (kt + 3) % NSTG); CP_COMMIT(); }

        uint32_t tA = sbase + (uint32_t)stg * STAGE_B;
        uint32_t tB = tA + TILE_B;

        #pragma unroll
        for (int ks = 0; ks < 2; ks++) {
            uint32_t ksx = (uint32_t)(ks * 32);
            uint32_t aq[2][4], bq[8][2];
            #pragma unroll
            for (int mt = 0; mt < 2; mt++)
                LDSM4(aq[mt], tA + (aoff[mt] ^ ksx));
            #pragma unroll
            for (int j = 0; j < 4; j++) {
                uint32_t rb[4];
                LDSM4(rb, tB + (boff[j] ^ ksx));
                bq[2*j][0] = rb[0]; bq[2*j][1] = rb[1];
                bq[2*j+1][0] = rb[2]; bq[2*j+1][1] = rb[3];
            }
            #pragma unroll
            for (int mt = 0; mt < 2; mt++)
                #pragma unroll
                for (int nt = 0; nt < 8; nt++)
                    mma_f16(acc[mt][nt], aq[mt], bq[nt]);
        }
    }
}

// fused k/v GEMM: z=0 -> k (fp32 out), z=1 -> v (fp16 out)
__global__ void __launch_bounds__(256)
gemm_kv(const __half* __restrict__ Xk, const __half* __restrict__ Wkt,
        const __half* __restrict__ Xv, const __half* __restrict__ Wvt,
        float* __restrict__ K, __half* __restrict__ V) {
    extern __shared__ uint32_t smem[];
    uint32_t sbase = smem_addr(smem);
    int tid = threadIdx.x;
    int z = blockIdx.z;
    int bm = blockIdx.y * BM, bn = blockIdx.x * BN;

    float acc[2][8][4];
    #pragma unroll
    for (int mt = 0; mt < 2; mt++)
        #pragma unroll
        for (int nt = 0; nt < 8; nt++)
            #pragma unroll
            for (int q = 0; q < 4; q++) acc[mt][nt][q] = 0.f;

    gemm_core(z ? Xv : Xk, z ? Wvt : Wkt, bm, bn, sbase, tid, acc);

    int warp = tid >> 5, lane = tid & 31;
    int wm = warp & 3, wn = warp >> 2;
    if (z == 0) {
        #pragma unroll
        for (int mt = 0; mt < 2; mt++) {
            int r0 = bm + wm*32 + mt*16 + (lane >> 2);
            #pragma unroll
            for (int nt = 0; nt < 8; nt++) {
                int c0 = bn + wn*64 + nt*8 + ((lane & 3) << 1);
                *(float2*)(&K[(size_t) r0     *E_DIM + c0]) = make_float2(acc[mt][nt][0], acc[mt][nt][1]);
                *(float2*)(&K[(size_t)(r0 + 8)*E_DIM + c0]) = make_float2(acc[mt][nt][2], acc[mt][nt][3]);
            }
        }
    } else {
        #pragma unroll
        for (int mt = 0; mt < 2; mt++) {
            int r0 = bm + wm*32 + mt*16 + (lane >> 2);
            #pragma unroll
            for (int nt = 0; nt < 8; nt++) {
                int c0 = bn + wn*64 + nt*8 + ((lane & 3) << 1);
                *(__half2*)(&V[(size_t) r0     *E_DIM + c0]) = __floats2half2_rn(acc[mt][nt][0], acc[mt][nt][1]);
                *(__half2*)(&V[(size_t)(r0 + 8)*E_DIM + c0]) = __floats2half2_rn(acc[mt][nt][2], acc[mt][nt][3]);
            }
        }
    }
}

// plain GEMM (fp32 out) for the output projection
__global__ void __launch_bounds__(256)
gemm_f16_1p(const __half* __restrict__ Aq, const __half* __restrict__ Bq,
            float* __restrict__ C) {
    extern __shared__ uint32_t smem[];
    uint32_t sbase = smem_addr(smem);
    int tid = threadIdx.x;
    int bm = blockIdx.y * BM, bn = blockIdx.x * BN;

    float acc[2][8][4];
    #pragma unroll
    for (int mt = 0; mt < 2; mt++)
        #pragma unroll
        for (int nt = 0; nt < 8; nt++)
            #pragma unroll
            for (int q = 0; q < 4; q++) acc[mt][nt][q] = 0.f;

    gemm_core(Aq, Bq, bm, bn, sbase, tid, acc);

    int warp = tid >> 5, lane = tid & 31;
    int wm = warp & 3, wn = warp >> 2;
    #pragma unroll
    for (int mt = 0; mt < 2; mt++) {
        int r0 = bm + wm*32 + mt*16 + (lane >> 2);
        #pragma unroll
        for (int nt = 0; nt < 8; nt++) {
            int c0 = bn + wn*64 + nt*8 + ((lane & 3) << 1);
            *(float2*)(&C[(size_t) r0     *E_DIM + c0]) = make_float2(acc[mt][nt][0], acc[mt][nt][1]);
            *(float2*)(&C[(size_t)(r0 + 8)*E_DIM + c0]) = make_float2(acc[mt][nt][2], acc[mt][nt][3]);
        }
    }
}

// ============================================================
// 3) chunked associative exp-scan (k fp32, v fp16)
// ============================================================
__device__ __forceinline__ void scan_step(float& a, float& b, float& p,
                                          float w, float k, float v) {
    float pw = p + w;
    float d  = pw - k;
    float e  = __expf(-fabsf(d));
    float e1 = (d >= 0.f) ? 1.f : e;
    float e2 = (d >= 0.f) ? e   : 1.f;
    a = a*e1 + v*e2;
    b = b*e1 + e2;
    p = fmaxf(pw, k);
}

// combine left (aL,bL,pL) with right (a,b,p); right covers cw chunks -> decay left
__device__ __forceinline__ void seg_combine(float aL, float bL, float pL,
                                            float& a, float& b, float& p,
                                            float cwLw) {
    float pw = pL + cwLw;
    float d  = pw - p;
    float e  = __expf(-fabsf(d));
    float e1 = (d >= 0.f) ? 1.f : e;
    float e2 = (d >= 0.f) ? e   : 1.f;
    a = aL*e1 + a*e2;
    b = bL*e1 + b*e2;
    p = fmaxf(pw, p);
}

__device__ __forceinline__ void load_v4(size_t off, float v[4]) {
    uint2 raw = *(const uint2*)((const unsigned short*)g_vh + off);
    float2 f01 = __half22float2(*(__half2*)&raw.x);
    float2 f23 = __half22float2(*(__half2*)&raw.y);
    v[0] = f01.x; v[1] = f01.y; v[2] = f23.x; v[3] = f23.y;
}

__global__ void scan_pass1(const float* __restrict__ time_decay) {
    int tid = blockIdx.x * blockDim.x + threadIdx.x;
    int c = tid >> 11, ch4 = tid & (CH4 - 1);
    int ch = ch4 * 4;
    int e  = ch & (E_DIM - 1);
    float4 w4 = *(const float4*)(time_decay + e);
    float a[4] = {0.f,0.f,0.f,0.f}, b[4] = {0.f,0.f,0.f,0.f};
    float p[4] = {-1e30f,-1e30f,-1e30f,-1e30f};
    float wv[4] = {w4.x, w4.y, w4.z, w4.w};
    int base = c * CLEN;
    for (int t0 = 0; t0 < CLEN; t0 += 4) {
        float4 kk[4]; float vv[4][4];
        #pragma unroll
        for (int i = 0; i < 4; i++) {
            size_t off = (size_t)(base + t0 + i) * CH + ch;
            kk[i] = *(const float4*)(g_k + off);
            load_v4(off, vv[i]);
        }
        #pragma unroll
        for (int i = 0; i < 4; i++) {
            scan_step(a[0], b[0], p[0], wv[0], kk[i].x, vv[i][0]);
            scan_step(a[1], b[1], p[1], wv[1], kk[i].y, vv[i][1]);
            scan_step(a[2], b[2], p[2], wv[2], kk[i].z, vv[i][2]);
            scan_step(a[3], b[3], p[3], wv[3], kk[i].w, vv[i][3]);
        }
    }
    *(float4*)(g_agg +               c*CH + ch) = make_float4(a[0],a[1],a[2],a[3]);
    *(float4*)(g_agg +   NCHUNK*CH + c*CH + ch) = make_float4(b[0],b[1],b[2],b[3]);
    *(float4*)(g_agg + 2*NCHUNK*CH + c*CH + ch) = make_float4(p[0],p[1],p[2],p[3]);
}

// warp-parallel exclusive scan over NCHUNK=128 chunks, smem-staged coalesced I/O.
// block = 256 threads = 8 warps = 8 channels; 4 chunks per lane.
__global__ void scan_pass2(const float* __restrict__ time_decay) {
    __shared__ float sa[NCHUNK][9];
    __shared__ float sb[NCHUNK][9];
    __shared__ float sp[NCHUNK][9];
    int ch0 = blockIdx.x * 8;
    int tid = threadIdx.x;

    // coalesced gather: thread t -> chunk t/8, channel t%8 (8 floats per 32B sector)
    #pragma unroll
    for (int i = 0; i < NCHUNK*8/256; i++) {
        int idx = tid + i*256;
        int c = idx >> 3, j = idx & 7;
        sa[c][j] = g_agg[              c*CH + ch0 + j];
        sb[c][j] = g_agg[  NCHUNK*CH + c*CH + ch0 + j];
        sp[c][j] = g_agg[2*NCHUNK*CH + c*CH + ch0 + j];
    }
    __syncthreads();

    int w = tid >> 5, lane = tid & 31;
    float wdec = time_decay[(ch0 + w) & (E_DIM - 1)];
    float Lw = (float)CLEN * wdec;
    int cbase = lane * 4;

    float la[4], lb[4], lp[4];
    #pragma unroll
    for (int i = 0; i < 4; i++) {
        la[i] = sa[cbase+i][w]; lb[i] = sb[cbase+i][w]; lp[i] = sp[cbase+i][w];
    }
    // lane-segment aggregate (covers 4 chunks)
    float A = la[0], B = lb[0], P = lp[0];
    #pragma unroll
    for (int i = 1; i < 4; i++) {
        float a2 = la[i], b2 = lb[i], p2 = lp[i];
        seg_combine(A, B, P, a2, b2, p2, Lw);
        A = a2; B = b2; P = p2;
    }
    int cnt = 4;
    // inclusive Kogge-Stone over lanes
    #pragma unroll
    for (int d = 1; d < 32; d <<= 1) {
        float aL = __shfl_up_sync(0xffffffffu, A, d);
        float bL = __shfl_up_sync(0xffffffffu, B, d);
        float pL = __shfl_up_sync(0xffffffffu, P, d);
        int   cL = __shfl_up_sync(0xffffffffu, cnt, d);
        if (lane >= d) {
            seg_combine(aL, bL, pL, A, B, P, (float)cnt * Lw);
            cnt += cL;
        }
    }
    // exclusive prefix for this lane's segment
    float ae = __shfl_up_sync(0xffffffffu, A, 1);
    float be = __shfl_up_sync(0xffffffffu, B, 1);
    float pe = __shfl_up_sync(0xffffffffu, P, 1);
    if (lane == 0) { ae = 0.f; be = 0.f; pe = -1e30f; }
    // per-chunk exclusive prefixes within the lane segment
    #pragma unroll
    for (int i = 0; i < 4; i++) {
        sa[cbase+i][w] = ae; sb[cbase+i][w] = be; sp[cbase+i][w] = pe;
        if (i < 3) {
            float a2 = la[i], b2 = lb[i], p2 = lp[i];
            seg_combine(ae, be, pe, a2, b2, p2, Lw);
            ae = a2; be = b2; pe = p2;
        }
    }
    __syncthreads();

    // coalesced scatter
    #pragma unroll
    for (int i = 0; i < NCHUNK*8/256; i++) {
        int idx = tid + i*256;
        int c = idx >> 3, j = idx & 7;
        g_pre[              c*CH + ch0 + j] = sa[c][j];
        g_pre[  NCHUNK*CH + c*CH + ch0 + j] = sb[c][j];
        g_pre[2*NCHUNK*CH + c*CH + ch0 + j] = sp[c][j];
    }
}

__global__ void scan_pass3(const float* __restrict__ time_decay,
                           const float* __restrict__ time_first) {
    int tid = blockIdx.x * blockDim.x + threadIdx.x;
    int c = tid >> 11, ch4 = tid & (CH4 - 1);
    int ch = ch4 * 4;
    int e  = ch & (E_DIM - 1);
    float4 w4 = *(const float4*)(time_decay + e);
    float4 u4 = *(const float4*)(time_first + e);
    float wv[4] = {w4.x, w4.y, w4.z, w4.w};
    float uv[4] = {u4.x, u4.y, u4.z, u4.w};
    float4 a4 = *(const float4*)(g_pre +               c*CH + ch);
    float4 b4 = *(const float4*)(g_pre +   NCHUNK*CH + c*CH + ch);
    float4 p4 = *(const float4*)(g_pre + 2*NCHUNK*CH + c*CH + ch);
    float a[4] = {a4.x,a4.y,a4.z,a4.w};
    float b[4] = {b4.x,b4.y,b4.z,b4.w};
    float p[4] = {p4.x,p4.y,p4.z,p4.w};
    int base = c * CLEN;
    for (int t0 = 0; t0 < CLEN; t0 += 4) {
        float4 kk[4]; float vv[4][4];
        #pragma unroll
        for (int i = 0; i < 4; i++) {
            size_t off = (size_t)(base + t0 + i) * CH + ch;
            kk[i] = *(const float4*)(g_k + off);
            load_v4(off, vv[i]);
        }
        #pragma unroll
        for (int i = 0; i < 4; i++) {
            float kv[4] = {kk[i].x, kk[i].y, kk[i].z, kk[i].w};
            ushort4 outq;
            unsigned short qs[4];
            #pragma unroll
            for (int j = 0; j < 4; j++) {
                scan_step(a[j], b[j], p[j], wv[j], kv[j], vv[i][j]);
                float kb = kv[j] + uv[j] + wv[j];
                float d2 = p[j] - kb;
                float eo = __expf(-fabsf(d2));
                float o1 = (d2 >= 0.f) ? 1.f : eo;
                float o2 = (d2 >= 0.f) ? eo  : 1.f;
                float cn = a[j]*o1 + vv[i][j]*o2;
                float dn = b[j]*o1 + o2;
                qs[j] = __half_as_ushort(__float2half_rn(__fdividef(cn, dn)));
            }
            outq.x = qs[0]; outq.y = qs[1]; outq.z = qs[2]; outq.w = qs[3];
            size_t off = (size_t)(base + t0 + i) * CH + ch;
            *(ushort4*)((unsigned short*)g_r + off) = outq;
        }
    }
}

// ============================================================
// launch
// ============================================================
extern "C" void kernel_launch(void* const* d_in, const int* in_sizes, int n_in,
                              void* d_out, int out_size) {
    const float* x     = (const float*)d_in[0];
    const float* tmrkv = (const float*)d_in[1];
    const float* Wk    = (const float*)d_in[2];
    const float* Wv    = (const float*)d_in[3];
    const float* td    = (const float*)d_in[4];
    const float* tf    = (const float*)d_in[5];
    const float* Wout  = (const float*)d_in[6];
    float* out = (float*)d_out;

    cudaFuncSetAttribute(gemm_kv,
                         cudaFuncAttributeMaxDynamicSharedMemorySize, GEMM_SMEM);
    cudaFuncSetAttribute(gemm_f16_1p,
                         cudaFuncAttributeMaxDynamicSharedMemorySize, GEMM_SMEM);

    __half *p_xk, *p_xv, *p_r, *p_wk, *p_wv, *p_wo, *p_vh;
    float *p_k;
    cudaGetSymbolAddress((void**)&p_xk, g_xk);
    cudaGetSymbolAddress((void**)&p_xv, g_xv);
    cudaGetSymbolAddress((void**)&p_r,  g_r);
    cudaGetSymbolAddress((void**)&p_wk, g_wkt);
    cudaGetSymbolAddress((void**)&p_wv, g_wvt);
    cudaGetSymbolAddress((void**)&p_wo, g_wot);
    cudaGetSymbolAddress((void**)&p_k,  g_k);
    cudaGetSymbolAddress((void**)&p_vh, g_vh);

    // 1) fused prep: mix + 3x weight transpose
    prep_kernel<<<MIXB + 3*1024, 256>>>(x, tmrkv, Wk, Wv, Wout);

    // 2) fused k/v GEMM
    dim3 kvgrid(E_DIM/BN, M_TOT/BM, 2);   // (8, 128, 2)
    gemm_kv<<<kvgrid, 256, GEMM_SMEM>>>(p_xk, p_wk, p_xv, p_wv, p_k, p_vh);

    // 3) scan
    scan_pass1<<<(NCHUNK*CH4)/256, 256>>>(td);
    scan_pass2<<<CH/8, 256>>>(td);
    scan_pass3<<<(NCHUNK*CH4)/256, 256>>>(td, tf);

    // 4) out = rwkv @ Wout
    dim3 ggrid(E_DIM/BN, M_TOT/BM);
    gemm_f16_1p<<<ggrid, 256, GEMM_SMEM>>>(p_r, p_wo, out);
}

// round 14
// speedup vs baseline: 1.2028x; 1.0075x over previous
#include <cuda_runtime.h>
#include <cuda_fp16.h>
#include <cstdint>
#include <cstddef>

#define S_LEN 2048
#define B_DIM 8
#define E_DIM 1024
#define M_TOT (S_LEN*B_DIM)      // 16384
#define CH    (B_DIM*E_DIM)      // 8192
#define NCHUNK 128
#define CLEN  (S_LEN/NCHUNK)     // 16
#define CH4   (CH/4)             // 2048

// ---------------- scratch (device globals; no allocation allowed) ------------
__device__ __half g_xk[(size_t)M_TOT*E_DIM];
__device__ __half g_xv[(size_t)M_TOT*E_DIM];
__device__ __half g_r [(size_t)M_TOT*E_DIM];
__device__ __half g_kh[(size_t)M_TOT*E_DIM];
__device__ __half g_vh[(size_t)M_TOT*E_DIM];
__device__ __half g_wkt[(size_t)E_DIM*E_DIM];
__device__ __half g_wvt[(size_t)E_DIM*E_DIM];
__device__ __half g_wot[(size_t)E_DIM*E_DIM];
__device__ float g_agg[3*NCHUNK*CH];
__device__ float g_pre[3*NCHUNK*CH];

// ---------------- helpers ----------------------------------------------------
__device__ __forceinline__ uint32_t smem_addr(const void* p) {
    uint32_t a;
    asm("{ .reg .u64 t; cvta.to.shared.u64 t, %1; cvt.u32.u64 %0, t; }" : "=r"(a) : "l"(p));
    return a;
}
#define CP_ASYNC16(dst, src) \
    asm volatile("cp.async.cg.shared.global [%0], [%1], 16;" :: "r"(dst), "l"(src) : "memory")
#define CP_COMMIT() asm volatile("cp.async.commit_group;" ::: "memory")
#define CP_WAIT(n)  asm volatile("cp.async.wait_group %0;" :: "n"(n) : "memory")

#define LDSM4(r, addr) \
    asm volatile("ldmatrix.sync.aligned.m8n8.x4.shared.b16 {%0,%1,%2,%3}, [%4];" \
        : "=r"((r)[0]), "=r"((r)[1]), "=r"((r)[2]), "=r"((r)[3]) : "r"(addr))

__device__ __forceinline__ void mma_f16(float c[4], const uint32_t a[4], const uint32_t b[2]) {
    asm volatile(
        "mma.sync.aligned.m16n8k16.row.col.f32.f16.f16.f32 "
        "{%0,%1,%2,%3}, {%4,%5,%6,%7}, {%8,%9}, {%0,%1,%2,%3};\n"
        : "+f"(c[0]), "+f"(c[1]), "+f"(c[2]), "+f"(c[3])
        : "r"(a[0]), "r"(a[1]), "r"(a[2]), "r"(a[3]), "r"(b[0]), "r"(b[1]));
}

// ============================================================
// 1) fused prep: token mix + fp16 quantize  AND  3x weight transpose
// ============================================================
#define MIXB (M_TOT*E_DIM/4/256)   // 16384

__global__ void prep_kernel(const float* __restrict__ x,
                            const float* __restrict__ tmrkv,
                            const float* __restrict__ Wk,
                            const float* __restrict__ Wv,
                            const float* __restrict__ Wout) {
    __shared__ float t[32][33];
    int blk = blockIdx.x;
    int tid = threadIdx.x;

    if (blk < MIXB) {
        int i4  = blk * 256 + tid;
        int idx = i4 * 4;
        int e   = idx & (E_DIM - 1);
        float4 xc = *(const float4*)(x + idx);
        float4 xp = make_float4(0.f, 0.f, 0.f, 0.f);
        if (idx >= CH) xp = *(const float4*)(x + idx - CH);
        float4 mk = *(const float4*)(tmrkv + E_DIM   + e);
        float4 mv = *(const float4*)(tmrkv + 2*E_DIM + e);
        float ok[4], ov[4];
        ok[0] = mk.x*xc.x + (1.f-mk.x)*xp.x;  ov[0] = mv.x*xc.x + (1.f-mv.x)*xp.x;
        ok[1] = mk.y*xc.y + (1.f-mk.y)*xp.y;  ov[1] = mv.y*xc.y + (1.f-mv.y)*xp.y;
        ok[2] = mk.z*xc.z + (1.f-mk.z)*xp.z;  ov[2] = mv.z*xc.z + (1.f-mv.z)*xp.z;
        ok[3] = mk.w*xc.w + (1.f-mk.w)*xp.w;  ov[3] = mv.w*xc.w + (1.f-mv.w)*xp.w;
        ushort4 kq, vq;
        kq.x = __half_as_ushort(__float2half_rn(ok[0]));
        kq.y = __half_as_ushort(__float2half_rn(ok[1]));
        kq.z = __half_as_ushort(__float2half_rn(ok[2]));
        kq.w = __half_as_ushort(__float2half_rn(ok[3]));
        vq.x = __half_as_ushort(__float2half_rn(ov[0]));
        vq.y = __half_as_ushort(__float2half_rn(ov[1]));
        vq.z = __half_as_ushort(__float2half_rn(ov[2]));
        vq.w = __half_as_ushort(__float2half_rn(ov[3]));
        *(ushort4*)((unsigned short*)g_xk + idx) = kq;
        *(ushort4*)((unsigned short*)g_xv + idx) = vq;
    } else {
        int wb   = blk - MIXB;
        int widx = wb >> 10;          // 0,1,2
        int tb   = wb & 1023;
        const float* W = (widx == 0) ? Wk : (widx == 1) ? Wv : Wout;
        __half* T = (widx == 0) ? g_wkt : (widx == 1) ? g_wvt : g_wot;
        int bx = (tb & 31) * 32;      // n block
        int by = (tb >> 5) * 32;      // k block
        int tx = tid & 31, ty = tid >> 5;   // 32 x 8
        for (int j = ty; j < 32; j += 8)
            t[j][tx] = W[(size_t)(by + j) * E_DIM + bx + tx];
        __syncthreads();
        for (int j = ty; j < 32; j += 8) {
            float v = t[tx][j];
            T[(size_t)(bx + j) * E_DIM + by + tx] = __float2half_rn(v);
        }
    }
}

// ============================================================
// 2) 1-product fp16 GEMM core (128x128, 256 thr, NSTG=4)
// ============================================================
#define BM 128
#define BN 128
#define BK 32
#define TILE_B 8192
#define STAGE_B (2*TILE_B)         // 16384
#define NSTG 4
#define GEMM_SMEM (NSTG*STAGE_B)   // 65536 -> 2 CTAs/SM

__device__ __forceinline__ void gemm_core(const __half* __restrict__ Aq,
                                          const __half* __restrict__ Bq,
                                          int bm, int bn,
                                          uint32_t sbase, int tid,
                                          float acc[2][8][4]) {
    int warp = tid >> 5, lane = tid & 31;
    int wm = warp & 3, wn = warp >> 2;

    const char* srcs[2] = {
        (const char*)(Aq + (size_t)bm * E_DIM),
        (const char*)(Bq + (size_t)bn * E_DIM) };

    auto load_tile = [&](int kt, int stg) {
        uint32_t dst0 = sbase + (uint32_t)stg * STAGE_B;
        int koff = kt * (BK*2);
        #pragma unroll
        for (int arr = 0; arr < 2; arr++) {
            #pragma unroll
            for (int i = 0; i < 2; i++) {
                int f = tid + i*256;
                int row = f >> 2, ch = f & 3;
                int sw = ch ^ ((row >> 1) & 3);
                uint32_t dst = dst0 + arr*TILE_B + row*64 + sw*16;
                const char* src = srcs[arr] + (size_t)row * (E_DIM*2) + koff + ch*16;
                CP_ASYNC16(dst, src);
            }
        }
    };

    int lm = lane & 7, lg = lane >> 3;
    uint32_t aoff[2];
    #pragma unroll
    for (int mt = 0; mt < 2; mt++) {
        int row = wm*32 + mt*16 + (lg & 1)*8 + lm;
        int swc = (lg >> 1) ^ ((row >> 1) & 3);
        aoff[mt] = (uint32_t)(row*64 + swc*16);
    }
    uint32_t boff[4];
    #pragma unroll
    for (int j = 0; j < 4; j++) {
        int row = wn*64 + j*16 + (lg >> 1)*8 + lm;
        int swc = (lg & 1) ^ ((row >> 1) & 3);
        boff[j] = (uint32_t)(row*64 + swc*16);
    }

    const int NK = E_DIM / BK;   // 32
    load_tile(0, 0); CP_COMMIT();
    load_tile(1, 1); CP_COMMIT();
    load_tile(2, 2); CP_COMMIT();

    for (int kt = 0; kt < NK; kt++) {
        int stg = kt % NSTG;
        if (kt == NK - 1) { CP_WAIT(0); } else { CP_WAIT(2); }
        __syncthreads();
        if (kt + 3 < NK) { load_tile(kt + 3, (kt + 3) % NSTG); CP_COMMIT(); }

        uint32_t tA = sbase + (uint32_t)stg * STAGE_B;
        uint32_t tB = tA + TILE_B;

        #pragma unroll
        for (int ks = 0; ks < 2; ks++) {
            uint32_t ksx = (uint32_t)(ks * 32);
            uint32_t aq[2][4], bq[8][2];
            #pragma unroll
            for (int mt = 0; mt < 2; mt++)
                LDSM4(aq[mt], tA + (aoff[mt] ^ ksx));
            #pragma unroll
            for (int j = 0; j < 4; j++) {
                uint32_t rb[4];
                LDSM4(rb, tB + (boff[j] ^ ksx));
                bq[2*j][0] = rb[0]; bq[2*j][1] = rb[1];
                bq[2*j+1][0] = rb[2]; bq[2*j+1][1] = rb[3];
            }
            #pragma unroll
            for (int mt = 0; mt < 2; mt++)
                #pragma unroll
                for (int nt = 0; nt < 8; nt++)
                    mma_f16(acc[mt][nt], aq[mt], bq[nt]);
        }
    }
}

// fused k/v GEMM: z=0 -> k, z=1 -> v, both fp16 out
__global__ void __launch_bounds__(256)
gemm_kv(const __half* __restrict__ Xk, const __half* __restrict__ Wkt,
        const __half* __restrict__ Xv, const __half* __restrict__ Wvt,
        __half* __restrict__ K, __half* __restrict__ V) {
    extern __shared__ uint32_t smem[];
    uint32_t sbase = smem_addr(smem);
    int tid = threadIdx.x;
    int z = blockIdx.z;
    int bm = blockIdx.y * BM, bn = blockIdx.x * BN;

    float acc[2][8][4];
    #pragma unroll
    for (int mt = 0; mt < 2; mt++)
        #pragma unroll
        for (int nt = 0; nt < 8; nt++)
            #pragma unroll
            for (int q = 0; q < 4; q++) acc[mt][nt][q] = 0.f;

    gemm_core(z ? Xv : Xk, z ? Wvt : Wkt, bm, bn, sbase, tid, acc);

    __half* O = z ? V : K;
    int warp = tid >> 5, lane = tid & 31;
    int wm = warp & 3, wn = warp >> 2;
    #pragma unroll
    for (int mt = 0; mt < 2; mt++) {
        int r0 = bm + wm*32 + mt*16 + (lane >> 2);
        #pragma unroll
        for (int nt = 0; nt < 8; nt++) {
            int c0 = bn + wn*64 + nt*8 + ((lane & 3) << 1);
            *(__half2*)(&O[(size_t) r0     *E_DIM + c0]) = __floats2half2_rn(acc[mt][nt][0], acc[mt][nt][1]);
            *(__half2*)(&O[(size_t)(r0 + 8)*E_DIM + c0]) = __floats2half2_rn(acc[mt][nt][2], acc[mt][nt][3]);
        }
    }
}

// plain GEMM (fp32 out) for the output projection
__global__ void __launch_bounds__(256)
gemm_f16_1p(const __half* __restrict__ Aq, const __half* __restrict__ Bq,
            float* __restrict__ C) {
    extern __shared__ uint32_t smem[];
    uint32_t sbase = smem_addr(smem);
    int tid = threadIdx.x;
    int bm = blockIdx.y * BM, bn = blockIdx.x * BN;

    float acc[2][8][4];
    #pragma unroll
    for (int mt = 0; mt < 2; mt++)
        #pragma unroll
        for (int nt = 0; nt < 8; nt++)
            #pragma unroll
            for (int q = 0; q < 4; q++) acc[mt][nt][q] = 0.f;

    gemm_core(Aq, Bq, bm, bn, sbase, tid, acc);

    int warp = tid >> 5, lane = tid & 31;
    int wm = warp & 3, wn = warp >> 2;
    #pragma unroll
    for (int mt = 0; mt < 2; mt++) {
        int r0 = bm + wm*32 + mt*16 + (lane >> 2);
        #pragma unroll
        for (int nt = 0; nt < 8; nt++) {
            int c0 = bn + wn*64 + nt*8 + ((lane & 3) << 1);
            *(float2*)(&C[(size_t) r0     *E_DIM + c0]) = make_float2(acc[mt][nt][0], acc[mt][nt][1]);
            *(float2*)(&C[(size_t)(r0 + 8)*E_DIM + c0]) = make_float2(acc[mt][nt][2], acc[mt][nt][3]);
        }
    }
}

// ============================================================
// 3) chunked associative exp-scan (k, v fp16)
// ============================================================
__device__ __forceinline__ void scan_step(float& a, float& b, float& p,
                                          float w, float k, float v) {
    float pw = p + w;
    float d  = pw - k;
    float e  = __expf(-fabsf(d));
    float e1 = (d >= 0.f) ? 1.f : e;
    float e2 = (d >= 0.f) ? e   : 1.f;
    a = a*e1 + v*e2;
    b = b*e1 + e2;
    p = fmaxf(pw, k);
}

__device__ __forceinline__ void seg_combine(float aL, float bL, float pL,
                                            float& a, float& b, float& p,
                                            float cwLw) {
    float pw = pL + cwLw;
    float d  = pw - p;
    float e  = __expf(-fabsf(d));
    float e1 = (d >= 0.f) ? 1.f : e;
    float e2 = (d >= 0.f) ? e   : 1.f;
    a = aL*e1 + a*e2;
    b = bL*e1 + b*e2;
    p = fmaxf(pw, p);
}

__device__ __forceinline__ void load_h4(const __half* base, size_t off, float v[4]) {
    uint2 raw = *(const uint2*)((const unsigned short*)base + off);
    float2 f01 = __half22float2(*(__half2*)&raw.x);
    float2 f23 = __half22float2(*(__half2*)&raw.y);
    v[0] = f01.x; v[1] = f01.y; v[2] = f23.x; v[3] = f23.y;
}

__global__ void scan_pass1(const float* __restrict__ time_decay) {
    int tid = blockIdx.x * blockDim.x + threadIdx.x;
    int c = tid >> 11, ch4 = tid & (CH4 - 1);
    int ch = ch4 * 4;
    int e  = ch & (E_DIM - 1);
    float4 w4 = *(const float4*)(time_decay + e);
    float a[4] = {0.f,0.f,0.f,0.f}, b[4] = {0.f,0.f,0.f,0.f};
    float p[4] = {-1e30f,-1e30f,-1e30f,-1e30f};
    float wv[4] = {w4.x, w4.y, w4.z, w4.w};
    int base = c * CLEN;
    for (int t0 = 0; t0 < CLEN; t0 += 4) {
        float kk[4][4], vv[4][4];
        #pragma unroll
        for (int i = 0; i < 4; i++) {
            size_t off = (size_t)(base + t0 + i) * CH + ch;
            load_h4(g_kh, off, kk[i]);
            load_h4(g_vh, off, vv[i]);
        }
        #pragma unroll
        for (int i = 0; i < 4; i++) {
            scan_step(a[0], b[0], p[0], wv[0], kk[i][0], vv[i][0]);
            scan_step(a[1], b[1], p[1], wv[1], kk[i][1], vv[i][1]);
            scan_step(a[2], b[2], p[2], wv[2], kk[i][2], vv[i][2]);
            scan_step(a[3], b[3], p[3], wv[3], kk[i][3], vv[i][3]);
        }
    }
    *(float4*)(g_agg +               c*CH + ch) = make_float4(a[0],a[1],a[2],a[3]);
    *(float4*)(g_agg +   NCHUNK*CH + c*CH + ch) = make_float4(b[0],b[1],b[2],b[3]);
    *(float4*)(g_agg + 2*NCHUNK*CH + c*CH + ch) = make_float4(p[0],p[1],p[2],p[3]);
}

// warp-parallel exclusive scan over NCHUNK=128 chunks, conflict-free smem.
// block = 256 threads = 8 warps = 8 channels; 4 chunks per lane.
// layout s[arr][channel][chunk] with row stride 132 (16B-aligned, conflict-free)
__global__ void scan_pass2(const float* __restrict__ time_decay) {
    __shared__ float s[3][8][132];
    int ch0 = blockIdx.x * 8;
    int tid = threadIdx.x;

    // coalesced gather: thread t -> chunk t/8, channel t%8
    #pragma unroll
    for (int i = 0; i < NCHUNK*8/256; i++) {
        int idx = tid + i*256;
        int c = idx >> 3, j = idx & 7;
        s[0][j][c] = g_agg[              c*CH + ch0 + j];
        s[1][j][c] = g_agg[  NCHUNK*CH + c*CH + ch0 + j];
        s[2][j][c] = g_agg[2*NCHUNK*CH + c*CH + ch0 + j];
    }
    __syncthreads();

    int w = tid >> 5, lane = tid & 31;
    float wdec = time_decay[(ch0 + w) & (E_DIM - 1)];
    float Lw = (float)CLEN * wdec;
    int cbase = lane * 4;

    float4 a4 = *(float4*)&s[0][w][cbase];
    float4 b4 = *(float4*)&s[1][w][cbase];
    float4 p4 = *(float4*)&s[2][w][cbase];
    float la[4] = {a4.x,a4.y,a4.z,a4.w};
    float lb[4] = {b4.x,b4.y,b4.z,b4.w};
    float lp[4] = {p4.x,p4.y,p4.z,p4.w};

    // lane-segment aggregate (covers 4 chunks)
    float A = la[0], B = lb[0], P = lp[0];
    #pragma unroll
    for (int i = 1; i < 4; i++) {
        float a2 = la[i], b2 = lb[i], p2 = lp[i];
        seg_combine(A, B, P, a2, b2, p2, Lw);
        A = a2; B = b2; P = p2;
    }
    int cnt = 4;
    #pragma unroll
    for (int d = 1; d < 32; d <<= 1) {
        float aL = __shfl_up_sync(0xffffffffu, A, d);
        float bL = __shfl_up_sync(0xffffffffu, B, d);
        float pL = __shfl_up_sync(0xffffffffu, P, d);
        int   cL = __shfl_up_sync(0xffffffffu, cnt, d);
        if (lane >= d) {
            seg_combine(aL, bL, pL, A, B, P, (float)cnt * Lw);
            cnt += cL;
        }
    }
    float ae = __shfl_up_sync(0xffffffffu, A, 1);
    float be = __shfl_up_sync(0xffffffffu, B, 1);
    float pe = __shfl_up_sync(0xffffffffu, P, 1);
    if (lane == 0) { ae = 0.f; be = 0.f; pe = -1e30f; }

    // per-chunk exclusive prefixes within the lane segment
    float oa[4], ob[4], op[4];
    #pragma unroll
    for (int i = 0; i < 4; i++) {
        oa[i] = ae; ob[i] = be; op[i] = pe;
        if (i < 3) {
            float a2 = la[i], b2 = lb[i], p2 = lp[i];
            seg_combine(ae, be, pe, a2, b2, p2, Lw);
            ae = a2; be = b2; pe = p2;
        }
    }
    *(float4*)&s[0][w][cbase] = make_float4(oa[0],oa[1],oa[2],oa[3]);
    *(float4*)&s[1][w][cbase] = make_float4(ob[0],ob[1],ob[2],ob[3]);
    *(float4*)&s[2][w][cbase] = make_float4(op[0],op[1],op[2],op[3]);
    __syncthreads();

    // coalesced scatter
    #pragma unroll
    for (int i = 0; i < NCHUNK*8/256; i++) {
        int idx = tid + i*256;
        int c = idx >> 3, j = idx & 7;
        g_pre[              c*CH + ch0 + j] = s[0][j][c];
        g_pre[  NCHUNK*CH + c*CH + ch0 + j] = s[1][j][c];
        g_pre[2*NCHUNK*CH + c*CH + ch0 + j] = s[2][j][c];
    }
}

__global__ void scan_pass3(const float* __restrict__ time_decay,
                           const float* __restrict__ time_first) {
    int tid = blockIdx.x * blockDim.x + threadIdx.x;
    int c = tid >> 11, ch4 = tid & (CH4 - 1);
    int ch = ch4 * 4;
    int e  = ch & (E_DIM - 1);
    float4 w4 = *(const float4*)(time_decay + e);
    float4 u4 = *(const float4*)(time_first + e);
    float wv[4] = {w4.x, w4.y, w4.z, w4.w};
    float uv[4] = {u4.x, u4.y, u4.z, u4.w};
    float4 a4 = *(const float4*)(g_pre +               c*CH + ch);
    float4 b4 = *(const float4*)(g_pre +   NCHUNK*CH + c*CH + ch);
    float4 p4 = *(const float4*)(g_pre + 2*NCHUNK*CH + c*CH + ch);
    float a[4] = {a4.x,a4.y,a4.z,a4.w};
    float b[4] = {b4.x,b4.y,b4.z,b4.w};
    float p[4] = {p4.x,p4.y,p4.z,p4.w};
    int base = c * CLEN;
    for (int t0 = 0; t0 < CLEN; t0 += 4) {
        float kk[4][4], vv[4][4];
        #pragma unroll
        for (int i = 0; i < 4; i++) {
            size_t off = (size_t)(base + t0 + i) * CH + ch;
            load_h4(g_kh, off, kk[i]);
            load_h4(g_vh, off, vv[i]);
        }
        #pragma unroll
        for (int i = 0; i < 4; i++) {
            ushort4 outq;
            unsigned short qs[4];
            #pragma unroll
            for (int j = 0; j < 4; j++) {
                scan_step(a[j], b[j], p[j], wv[j], kk[i][j], vv[i][j]);
                float kb = kk[i][j] + uv[j] + wv[j];
                float d2 = p[j] - kb;
                float eo = __expf(-fabsf(d2));
                float o1 = (d2 >= 0.f) ? 1.f : eo;
                float o2 = (d2 >= 0.f) ? eo  : 1.f;
                float cn = a[j]*o1 + vv[i][j]*o2;
                float dn = b[j]*o1 + o2;
                qs[j] = __half_as_ushort(__float2half_rn(__fdividef(cn, dn)));
            }
            outq.x = qs[0]; outq.y = qs[1]; outq.z = qs[2]; outq.w = qs[3];
            size_t off = (size_t)(base + t0 + i) * CH + ch;
            *(ushort4*)((unsigned short*)g_r + off) = outq;
        }
    }
}

// ============================================================
// launch
// ============================================================
extern "C" void kernel_launch(void* const* d_in, const int* in_sizes, int n_in,
                              void* d_out, int out_size) {
    const float* x     = (const float*)d_in[0];
    const float* tmrkv = (const float*)d_in[1];
    const float* Wk    = (const float*)d_in[2];
    const float* Wv    = (const float*)d_in[3];
    const float* td    = (const float*)d_in[4];
    const float* tf    = (const float*)d_in[5];
    const float* Wout  = (const float*)d_in[6];
    float* out = (float*)d_out;

    cudaFuncSetAttribute(gemm_kv,
                         cudaFuncAttributeMaxDynamicSharedMemorySize, GEMM_SMEM);
    cudaFuncSetAttribute(gemm_f16_1p,
                         cudaFuncAttributeMaxDynamicSharedMemorySize, GEMM_SMEM);

    __half *p_xk, *p_xv, *p_r, *p_wk, *p_wv, *p_wo, *p_kh, *p_vh;
    cudaGetSymbolAddress((void**)&p_xk, g_xk);
    cudaGetSymbolAddress((void**)&p_xv, g_xv);
    cudaGetSymbolAddress((void**)&p_r,  g_r);
    cudaGetSymbolAddress((void**)&p_wk, g_wkt);
    cudaGetSymbolAddress((void**)&p_wv, g_wvt);
    cudaGetSymbolAddress((void**)&p_wo, g_wot);
    cudaGetSymbolAddress((void**)&p_kh, g_kh);
    cudaGetSymbolAddress((void**)&p_vh, g_vh);

    // 1) fused prep: mix + 3x weight transpose
    prep_kernel<<<MIXB + 3*1024, 256>>>(x, tmrkv, Wk, Wv, Wout);

    // 2) fused k/v GEMM
    dim3 kvgrid(E_DIM/BN, M_TOT/BM, 2);   // (8, 128, 2)
    gemm_kv<<<kvgrid, 256, GEMM_SMEM>>>(p_xk, p_wk, p_xv, p_wv, p_kh, p_vh);

    // 3) scan
    scan_pass1<<<(NCHUNK*CH4)/256, 256>>>(td);
    scan_pass2<<<CH/8, 256>>>(td);
    scan_pass3<<<(NCHUNK*CH4)/256, 256>>>(td, tf);

    // 4) out = rwkv @ Wout
    dim3 ggrid(E_DIM/BN, M_TOT/BM);
    gemm_f16_1p<<<ggrid, 256, GEMM_SMEM>>>(p_r, p_wo, out);
}

// round 15
// speedup vs baseline: 1.2923x; 1.0744x over previous
#include <cuda_runtime.h>
#include <cuda_fp16.h>
#include <cstdint>
#include <cstddef>

#define S_LEN 2048
#define B_DIM 8
#define E_DIM 1024
#define M_TOT (S_LEN*B_DIM)      // 16384
#define CH    (B_DIM*E_DIM)      // 8192
#define NCHUNK 128
#define CLEN  (S_LEN/NCHUNK)     // 16
#define CH4   (CH/4)             // 2048

// ---------------- scratch (device globals; no allocation allowed) ------------
__device__ __half g_xk[(size_t)M_TOT*E_DIM];
__device__ __half g_xv[(size_t)M_TOT*E_DIM];
__device__ __half g_r [(size_t)M_TOT*E_DIM];
__device__ __half g_kh[(size_t)M_TOT*E_DIM];
__device__ __half g_vh[(size_t)M_TOT*E_DIM];
__device__ __half g_wkt[(size_t)E_DIM*E_DIM];
__device__ __half g_wvt[(size_t)E_DIM*E_DIM];
__device__ __half g_wot[(size_t)E_DIM*E_DIM];
__device__ float g_agg[3*NCHUNK*CH];
__device__ float g_pre[3*NCHUNK*CH];

// ---------------- helpers ----------------------------------------------------
__device__ __forceinline__ uint32_t smem_addr(const void* p) {
    uint32_t a;
    asm("{ .reg .u64 t; cvta.to.shared.u64 t, %1; cvt.u32.u64 %0, t; }" : "=r"(a) : "l"(p));
    return a;
}
#define CP_ASYNC16(dst, src) \
    asm volatile("cp.async.cg.shared.global [%0], [%1], 16;" :: "r"(dst), "l"(src) : "memory")
#define CP_COMMIT() asm volatile("cp.async.commit_group;" ::: "memory")
#define CP_WAIT(n)  asm volatile("cp.async.wait_group %0;" :: "n"(n) : "memory")

#define LDSM4(r, addr) \
    asm volatile("ldmatrix.sync.aligned.m8n8.x4.shared.b16 {%0,%1,%2,%3}, [%4];" \
        : "=r"((r)[0]), "=r"((r)[1]), "=r"((r)[2]), "=r"((r)[3]) : "r"(addr))

__device__ __forceinline__ void mma_f16(float c[4], const uint32_t a[4], const uint32_t b[2]) {
    asm volatile(
        "mma.sync.aligned.m16n8k16.row.col.f32.f16.f16.f32 "
        "{%0,%1,%2,%3}, {%4,%5,%6,%7}, {%8,%9}, {%0,%1,%2,%3};\n"
        : "+f"(c[0]), "+f"(c[1]), "+f"(c[2]), "+f"(c[3])
        : "r"(a[0]), "r"(a[1]), "r"(a[2]), "r"(a[3]), "r"(b[0]), "r"(b[1]));
}

// ============================================================
// 1) fused prep: token mix + fp16 quantize  AND  3x weight transpose
// ============================================================
#define MIXB (M_TOT*E_DIM/4/256)   // 16384

__global__ void prep_kernel(const float* __restrict__ x,
                            const float* __restrict__ tmrkv,
                            const float* __restrict__ Wk,
                            const float* __restrict__ Wv,
                            const float* __restrict__ Wout) {
    __shared__ float t[32][33];
    int blk = blockIdx.x;
    int tid = threadIdx.x;

    if (blk < MIXB) {
        int i4  = blk * 256 + tid;
        int idx = i4 * 4;
        int e   = idx & (E_DIM - 1);
        float4 xc = *(const float4*)(x + idx);
        float4 xp = make_float4(0.f, 0.f, 0.f, 0.f);
        if (idx >= CH) xp = *(const float4*)(x + idx - CH);
        float4 mk = *(const float4*)(tmrkv + E_DIM   + e);
        float4 mv = *(const float4*)(tmrkv + 2*E_DIM + e);
        float ok[4], ov[4];
        ok[0] = mk.x*xc.x + (1.f-mk.x)*xp.x;  ov[0] = mv.x*xc.x + (1.f-mv.x)*xp.x;
        ok[1] = mk.y*xc.y + (1.f-mk.y)*xp.y;  ov[1] = mv.y*xc.y + (1.f-mv.y)*xp.y;
        ok[2] = mk.z*xc.z + (1.f-mk.z)*xp.z;  ov[2] = mv.z*xc.z + (1.f-mv.z)*xp.z;
        ok[3] = mk.w*xc.w + (1.f-mk.w)*xp.w;  ov[3] = mv.w*xc.w + (1.f-mv.w)*xp.w;
        ushort4 kq, vq;
        kq.x = __half_as_ushort(__float2half_rn(ok[0]));
        kq.y = __half_as_ushort(__float2half_rn(ok[1]));
        kq.z = __half_as_ushort(__float2half_rn(ok[2]));
        kq.w = __half_as_ushort(__float2half_rn(ok[3]));
        vq.x = __half_as_ushort(__float2half_rn(ov[0]));
        vq.y = __half_as_ushort(__float2half_rn(ov[1]));
        vq.z = __half_as_ushort(__float2half_rn(ov[2]));
        vq.w = __half_as_ushort(__float2half_rn(ov[3]));
        *(ushort4*)((unsigned short*)g_xk + idx) = kq;
        *(ushort4*)((unsigned short*)g_xv + idx) = vq;
    } else {
        int wb   = blk - MIXB;
        int widx = wb >> 10;          // 0,1,2
        int tb   = wb & 1023;
        const float* W = (widx == 0) ? Wk : (widx == 1) ? Wv : Wout;
        __half* T = (widx == 0) ? g_wkt : (widx == 1) ? g_wvt : g_wot;
        int bx = (tb & 31) * 32;      // n block
        int by = (tb >> 5) * 32;      // k block
        int tx = tid & 31, ty = tid >> 5;   // 32 x 8
        for (int j = ty; j < 32; j += 8)
            t[j][tx] = W[(size_t)(by + j) * E_DIM + bx + tx];
        __syncthreads();
        for (int j = ty; j < 32; j += 8) {
            float v = t[tx][j];
            T[(size_t)(bx + j) * E_DIM + by + tx] = __float2half_rn(v);
        }
    }
}

// ============================================================
// 2) 1-product fp16 GEMM core (128x128 tile, BK=64, 256 thr, NSTG=3)
//    operand tile: [2 ksl][128 rows][64B], XOR swizzle per 64B row
// ============================================================
#define BM 128
#define BN 128
#define BK 64
#define TILE_B 16384               // 128 rows * 128 bytes
#define STAGE_B (2*TILE_B)         // 32768
#define NSTG 3
#define GEMM_SMEM (NSTG*STAGE_B)   // 98304 -> 2 CTAs/SM

__device__ __forceinline__ void gemm_core(const __half* __restrict__ Aq,
                                          const __half* __restrict__ Bq,
                                          int bm, int bn,
                                          uint32_t sbase, int tid,
                                          float acc[2][8][4]) {
    int warp = tid >> 5, lane = tid & 31;
    int wm = warp & 3, wn = warp >> 2;

    const char* srcs[2] = {
        (const char*)(Aq + (size_t)bm * E_DIM),
        (const char*)(Bq + (size_t)bn * E_DIM) };

    auto load_tile = [&](int kt, int stg) {
        uint32_t dst0 = sbase + (uint32_t)stg * STAGE_B;
        int koff = kt * (BK*2);    // 128 bytes per k-tile
        #pragma unroll
        for (int arr = 0; arr < 2; arr++) {
            #pragma unroll
            for (int i = 0; i < 4; i++) {
                int f = tid + i*256;         // 1024 chunk-loads per operand
                int row = f >> 3, chunk = f & 7;
                int ksl = chunk >> 2, ch = chunk & 3;
                int sw = ch ^ ((row >> 1) & 3);
                uint32_t dst = dst0 + arr*TILE_B + ksl*8192 + row*64 + sw*16;
                const char* src = srcs[arr] + (size_t)row * (E_DIM*2) + koff + chunk*16;
                CP_ASYNC16(dst, src);
            }
        }
    };

    int lm = lane & 7, lg = lane >> 3;
    uint32_t aoff[2];
    #pragma unroll
    for (int mt = 0; mt < 2; mt++) {
        int row = wm*32 + mt*16 + (lg & 1)*8 + lm;
        int swc = (lg >> 1) ^ ((row >> 1) & 3);
        aoff[mt] = (uint32_t)(row*64 + swc*16);
    }
    uint32_t boff[4];
    #pragma unroll
    for (int j = 0; j < 4; j++) {
        int row = wn*64 + j*16 + (lg >> 1)*8 + lm;
        int swc = (lg & 1) ^ ((row >> 1) & 3);
        boff[j] = (uint32_t)(row*64 + swc*16);
    }

    const int NK = E_DIM / BK;   // 16
    load_tile(0, 0); CP_COMMIT();
    load_tile(1, 1); CP_COMMIT();

    for (int kt = 0; kt < NK; kt++) {
        int stg = kt % NSTG;
        if (kt == NK - 1) { CP_WAIT(0); } else { CP_WAIT(1); }
        __syncthreads();
        if (kt + 2 < NK) { load_tile(kt + 2, (kt + 2) % NSTG); CP_COMMIT(); }

        uint32_t tA = sbase + (uint32_t)stg * STAGE_B;
        uint32_t tB = tA + TILE_B;

        #pragma unroll
        for (int ks = 0; ks < 4; ks++) {
            uint32_t ko = (uint32_t)((ks >> 1) * 8192);
            uint32_t ksx = (uint32_t)((ks & 1) * 32);
            uint32_t aq[2][4], bq[8][2];
            #pragma unroll
            for (int mt = 0; mt < 2; mt++)
                LDSM4(aq[mt], tA + ko + (aoff[mt] ^ ksx));
            #pragma unroll
            for (int j = 0; j < 4; j++) {
                uint32_t rb[4];
                LDSM4(rb, tB + ko + (boff[j] ^ ksx));
                bq[2*j][0] = rb[0]; bq[2*j][1] = rb[1];
                bq[2*j+1][0] = rb[2]; bq[2*j+1][1] = rb[3];
            }
            #pragma unroll
            for (int mt = 0; mt < 2; mt++)
                #pragma unroll
                for (int nt = 0; nt < 8; nt++)
                    mma_f16(acc[mt][nt], aq[mt], bq[nt]);
        }
    }
}

// fused k/v GEMM: z=0 -> k, z=1 -> v, both fp16 out
__global__ void __launch_bounds__(256)
gemm_kv(const __half* __restrict__ Xk, const __half* __restrict__ Wkt,
        const __half* __restrict__ Xv, const __half* __restrict__ Wvt,
        __half* __restrict__ K, __half* __restrict__ V) {
    extern __shared__ uint32_t smem[];
    uint32_t sbase = smem_addr(smem);
    int tid = threadIdx.x;
    int z = blockIdx.z;
    int bm = blockIdx.y * BM, bn = blockIdx.x * BN;

    float acc[2][8][4];
    #pragma unroll
    for (int mt = 0; mt < 2; mt++)
        #pragma unroll
        for (int nt = 0; nt < 8; nt++)
            #pragma unroll
            for (int q = 0; q < 4; q++) acc[mt][nt][q] = 0.f;

    gemm_core(z ? Xv : Xk, z ? Wvt : Wkt, bm, bn, sbase, tid, acc);

    __half* O = z ? V : K;
    int warp = tid >> 5, lane = tid & 31;
    int wm = warp & 3, wn = warp >> 2;
    #pragma unroll
    for (int mt = 0; mt < 2; mt++) {
        int r0 = bm + wm*32 + mt*16 + (lane >> 2);
        #pragma unroll
        for (int nt = 0; nt < 8; nt++) {
            int c0 = bn + wn*64 + nt*8 + ((lane & 3) << 1);
            *(__half2*)(&O[(size_t) r0     *E_DIM + c0]) = __floats2half2_rn(acc[mt][nt][0], acc[mt][nt][1]);
            *(__half2*)(&O[(size_t)(r0 + 8)*E_DIM + c0]) = __floats2half2_rn(acc[mt][nt][2], acc[mt][nt][3]);
        }
    }
}

// plain GEMM (fp32 out) for the output projection
__global__ void __launch_bounds__(256)
gemm_f16_1p(const __half* __restrict__ Aq, const __half* __restrict__ Bq,
            float* __restrict__ C) {
    extern __shared__ uint32_t smem[];
    uint32_t sbase = smem_addr(smem);
    int tid = threadIdx.x;
    int bm = blockIdx.y * BM, bn = blockIdx.x * BN;

    float acc[2][8][4];
    #pragma unroll
    for (int mt = 0; mt < 2; mt++)
        #pragma unroll
        for (int nt = 0; nt < 8; nt++)
            #pragma unroll
            for (int q = 0; q < 4; q++) acc[mt][nt][q] = 0.f;

    gemm_core(Aq, Bq, bm, bn, sbase, tid, acc);

    int warp = tid >> 5, lane = tid & 31;
    int wm = warp & 3, wn = warp >> 2;
    #pragma unroll
    for (int mt = 0; mt < 2; mt++) {
        int r0 = bm + wm*32 + mt*16 + (lane >> 2);
        #pragma unroll
        for (int nt = 0; nt < 8; nt++) {
            int c0 = bn + wn*64 + nt*8 + ((lane & 3) << 1);
            *(float2*)(&C[(size_t) r0     *E_DIM + c0]) = make_float2(acc[mt][nt][0], acc[mt][nt][1]);
            *(float2*)(&C[(size_t)(r0 + 8)*E_DIM + c0]) = make_float2(acc[mt][nt][2], acc[mt][nt][3]);
        }
    }
}

// ============================================================
// 3) chunked associative exp-scan (k, v fp16)
// ============================================================
__device__ __forceinline__ void scan_step(float& a, float& b, float& p,
                                          float w, float k, float v) {
    float pw = p + w;
    float d  = pw - k;
    float e  = __expf(-fabsf(d));
    float e1 = (d >= 0.f) ? 1.f : e;
    float e2 = (d >= 0.f) ? e   : 1.f;
    a = a*e1 + v*e2;
    b = b*e1 + e2;
    p = fmaxf(pw, k);
}

__device__ __forceinline__ void seg_combine(float aL, float bL, float pL,
                                            float& a, float& b, float& p,
                                            float cwLw) {
    float pw = pL + cwLw;
    float d  = pw - p;
    float e  = __expf(-fabsf(d));
    float e1 = (d >= 0.f) ? 1.f : e;
    float e2 = (d >= 0.f) ? e   : 1.f;
    a = aL*e1 + a*e2;
    b = bL*e1 + b*e2;
    p = fmaxf(pw, p);
}

__device__ __forceinline__ void load_h4(const __half* base, size_t off, float v[4]) {
    uint2 raw = *(const uint2*)((const unsigned short*)base + off);
    float2 f01 = __half22float2(*(__half2*)&raw.x);
    float2 f23 = __half22float2(*(__half2*)&raw.y);
    v[0] = f01.x; v[1] = f01.y; v[2] = f23.x; v[3] = f23.y;
}

__global__ void scan_pass1(const float* __restrict__ time_decay) {
    int tid = blockIdx.x * blockDim.x + threadIdx.x;
    int c = tid >> 11, ch4 = tid & (CH4 - 1);
    int ch = ch4 * 4;
    int e  = ch & (E_DIM - 1);
    float4 w4 = *(const float4*)(time_decay + e);
    float a[4] = {0.f,0.f,0.f,0.f}, b[4] = {0.f,0.f,0.f,0.f};
    float p[4] = {-1e30f,-1e30f,-1e30f,-1e30f};
    float wv[4] = {w4.x, w4.y, w4.z, w4.w};
    int base = c * CLEN;
    for (int t0 = 0; t0 < CLEN; t0 += 4) {
        float kk[4][4], vv[4][4];
        #pragma unroll
        for (int i = 0; i < 4; i++) {
            size_t off = (size_t)(base + t0 + i) * CH + ch;
            load_h4(g_kh, off, kk[i]);
            load_h4(g_vh, off, vv[i]);
        }
        #pragma unroll
        for (int i = 0; i < 4; i++) {
            scan_step(a[0], b[0], p[0], wv[0], kk[i][0], vv[i][0]);
            scan_step(a[1], b[1], p[1], wv[1], kk[i][1], vv[i][1]);
            scan_step(a[2], b[2], p[2], wv[2], kk[i][2], vv[i][2]);
            scan_step(a[3], b[3], p[3], wv[3], kk[i][3], vv[i][3]);
        }
    }
    *(float4*)(g_agg +               c*CH + ch) = make_float4(a[0],a[1],a[2],a[3]);
    *(float4*)(g_agg +   NCHUNK*CH + c*CH + ch) = make_float4(b[0],b[1],b[2],b[3]);
    *(float4*)(g_agg + 2*NCHUNK*CH + c*CH + ch) = make_float4(p[0],p[1],p[2],p[3]);
}

// warp-parallel exclusive scan over NCHUNK=128 chunks, conflict-free smem.
__global__ void scan_pass2(const float* __restrict__ time_decay) {
    __shared__ float s[3][8][132];
    int ch0 = blockIdx.x * 8;
    int tid = threadIdx.x;

    #pragma unroll
    for (int i = 0; i < NCHUNK*8/256; i++) {
        int idx = tid + i*256;
        int c = idx >> 3, j = idx & 7;
        s[0][j][c] = g_agg[              c*CH + ch0 + j];
        s[1][j][c] = g_agg[  NCHUNK*CH + c*CH + ch0 + j];
        s[2][j][c] = g_agg[2*NCHUNK*CH + c*CH + ch0 + j];
    }
    __syncthreads();

    int w = tid >> 5, lane = tid & 31;
    float wdec = time_decay[(ch0 + w) & (E_DIM - 1)];
    float Lw = (float)CLEN * wdec;
    int cbase = lane * 4;

    float4 a4 = *(float4*)&s[0][w][cbase];
    float4 b4 = *(float4*)&s[1][w][cbase];
    float4 p4 = *(float4*)&s[2][w][cbase];
    float la[4] = {a4.x,a4.y,a4.z,a4.w};
    float lb[4] = {b4.x,b4.y,b4.z,b4.w};
    float lp[4] = {p4.x,p4.y,p4.z,p4.w};

    float A = la[0], B = lb[0], P = lp[0];
    #pragma unroll
    for (int i = 1; i < 4; i++) {
        float a2 = la[i], b2 = lb[i], p2 = lp[i];
        seg_combine(A, B, P, a2, b2, p2, Lw);
        A = a2; B = b2; P = p2;
    }
    int cnt = 4;
    #pragma unroll
    for (int d = 1; d < 32; d <<= 1) {
        float aL = __shfl_up_sync(0xffffffffu, A, d);
        float bL = __shfl_up_sync(0xffffffffu, B, d);
        float pL = __shfl_up_sync(0xffffffffu, P, d);
        int   cL = __shfl_up_sync(0xffffffffu, cnt, d);
        if (lane >= d) {
            seg_combine(aL, bL, pL, A, B, P, (float)cnt * Lw);
            cnt += cL;
        }
    }
    float ae = __shfl_up_sync(0xffffffffu, A, 1);
    float be = __shfl_up_sync(0xffffffffu, B, 1);
    float pe = __shfl_up_sync(0xffffffffu, P, 1);
    if (lane == 0) { ae = 0.f; be = 0.f; pe = -1e30f; }

    float oa[4], ob[4], op[4];
    #pragma unroll
    for (int i = 0; i < 4; i++) {
        oa[i] = ae; ob[i] = be; op[i] = pe;
        if (i < 3) {
            float a2 = la[i], b2 = lb[i], p2 = lp[i];
            seg_combine(ae, be, pe, a2, b2, p2, Lw);
            ae = a2; be = b2; pe = p2;
        }
    }
    *(float4*)&s[0][w][cbase] = make_float4(oa[0],oa[1],oa[2],oa[3]);
    *(float4*)&s[1][w][cbase] = make_float4(ob[0],ob[1],ob[2],ob[3]);
    *(float4*)&s[2][w][cbase] = make_float4(op[0],op[1],op[2],op[3]);
    __syncthreads();

    #pragma unroll
    for (int i = 0; i < NCHUNK*8/256; i++) {
        int idx = tid + i*256;
        int c = idx >> 3, j = idx & 7;
        g_pre[              c*CH + ch0 + j] = s[0][j][c];
        g_pre[  NCHUNK*CH + c*CH + ch0 + j] = s[1][j][c];
        g_pre[2*NCHUNK*CH + c*CH + ch0 + j] = s[2][j][c];
    }
}

__global__ void scan_pass3(const float* __restrict__ time_decay,
                           const float* __restrict__ time_first) {
    int tid = blockIdx.x * blockDim.x + threadIdx.x;
    int c = tid >> 11, ch4 = tid & (CH4 - 1);
    int ch = ch4 * 4;
    int e  = ch & (E_DIM - 1);
    float4 w4 = *(const float4*)(time_decay + e);
    float4 u4 = *(const float4*)(time_first + e);
    float wv[4] = {w4.x, w4.y, w4.z, w4.w};
    float uv[4] = {u4.x, u4.y, u4.z, u4.w};
    float4 a4 = *(const float4*)(g_pre +               c*CH + ch);
    float4 b4 = *(const float4*)(g_pre +   NCHUNK*CH + c*CH + ch);
    float4 p4 = *(const float4*)(g_pre + 2*NCHUNK*CH + c*CH + ch);
    float a[4] = {a4.x,a4.y,a4.z,a4.w};
    float b[4] = {b4.x,b4.y,b4.z,b4.w};
    float p[4] = {p4.x,p4.y,p4.z,p4.w};
    int base = c * CLEN;
    for (int t0 = 0; t0 < CLEN; t0 += 4) {
        float kk[4][4], vv[4][4];
        #pragma unroll
        for (int i = 0; i < 4; i++) {
            size_t off = (size_t)(base + t0 + i) * CH + ch;
            load_h4(g_kh, off, kk[i]);
            load_h4(g_vh, off, vv[i]);
        }
        #pragma unroll
        for (int i = 0; i < 4; i++) {
            ushort4 outq;
            unsigned short qs[4];
            #pragma unroll
            for (int j = 0; j < 4; j++) {
                scan_step(a[j], b[j], p[j], wv[j], kk[i][j], vv[i][j]);
                float kb = kk[i][j] + uv[j] + wv[j];
                float d2 = p[j] - kb;
                float eo = __expf(-fabsf(d2));
                float o1 = (d2 >= 0.f) ? 1.f : eo;
                float o2 = (d2 >= 0.f) ? eo  : 1.f;
                float cn = a[j]*o1 + vv[i][j]*o2;
                float dn = b[j]*o1 + o2;
                qs[j] = __half_as_ushort(__float2half_rn(__fdividef(cn, dn)));
            }
            outq.x = qs[0]; outq.y = qs[1]; outq.z = qs[2]; outq.w = qs[3];
            size_t off = (size_t)(base + t0 + i) * CH + ch;
            *(ushort4*)((unsigned short*)g_r + off) = outq;
        }
    }
}

// ============================================================
// launch
// ============================================================
extern "C" void kernel_launch(void* const* d_in, const int* in_sizes, int n_in,
                              void* d_out, int out_size) {
    const float* x     = (const float*)d_in[0];
    const float* tmrkv = (const float*)d_in[1];
    const float* Wk    = (const float*)d_in[2];
    const float* Wv    = (const float*)d_in[3];
    const float* td    = (const float*)d_in[4];
    const float* tf    = (const float*)d_in[5];
    const float* Wout  = (const float*)d_in[6];
    float* out = (float*)d_out;

    cudaFuncSetAttribute(gemm_kv,
                         cudaFuncAttributeMaxDynamicSharedMemorySize, GEMM_SMEM);
    cudaFuncSetAttribute(gemm_f16_1p,
                         cudaFuncAttributeMaxDynamicSharedMemorySize, GEMM_SMEM);

    __half *p_xk, *p_xv, *p_r, *p_wk, *p_wv, *p_wo, *p_kh, *p_vh;
    cudaGetSymbolAddress((void**)&p_xk, g_xk);
    cudaGetSymbolAddress((void**)&p_xv, g_xv);
    cudaGetSymbolAddress((void**)&p_r,  g_r);
    cudaGetSymbolAddress((void**)&p_wk, g_wkt);
    cudaGetSymbolAddress((void**)&p_wv, g_wvt);
    cudaGetSymbolAddress((void**)&p_wo, g_wot);
    cudaGetSymbolAddress((void**)&p_kh, g_kh);
    cudaGetSymbolAddress((void**)&p_vh, g_vh);

    // 1) fused prep: mix + 3x weight transpose
    prep_kernel<<<MIXB + 3*1024, 256>>>(x, tmrkv, Wk, Wv, Wout);

    // 2) fused k/v GEMM
    dim3 kvgrid(E_DIM/BN, M_TOT/BM, 2);   // (8, 128, 2)
    gemm_kv<<<kvgrid, 256, GEMM_SMEM>>>(p_xk, p_wk, p_xv, p_wv, p_kh, p_vh);

    // 3) scan
    scan_pass1<<<(NCHUNK*CH4)/256, 256>>>(td);
    scan_pass2<<<CH/8, 256>>>(td);
    scan_pass3<<<(NCHUNK*CH4)/256, 256>>>(td, tf);

    // 4) out = rwkv @ Wout
    dim3 ggrid(E_DIM/BN, M_TOT/BM);
    gemm_f16_1p<<<ggrid, 256, GEMM_SMEM>>>(p_r, p_wo, out);
}